// round 7
// baseline (speedup 1.0000x reference)
#include <cuda_runtime.h>
#include <math.h>

#define Bdim 32
#define Tdim 1024
#define DIdim 512
#define Hdim 512
#define NG (4*Hdim)

#define HROW 516                       // padded h row (floats)
#define H_SLICE_BYTES 16512u           // 8 rows * 516 * 4
#define H_BYTES 66048u                 // 32 rows * 516 * 4

// Scratch (device globals)
__device__ float    g_G[Tdim*Bdim*NG];        // [t][b][gate*512+j] = x@W + bias
__device__ unsigned g_A[Tdim*Bdim*DIdim];     // tf32(X) gathered, row m=t*32+b
__device__ unsigned g_Wt[DIdim*NG];           // tf32(W) fused [k][gate*512+c]
__device__ unsigned g_Ut[Hdim*NG];            // tf32(U) fused block-interleaved
__device__ float    g_bias[NG];
__device__ __align__(16) float g_h[2][32*HROW];  // fp32 h, PADDED layout, double-buffered
__device__ unsigned g_flag[128];              // per-CTA arrival flags (monotonic)
__device__ unsigned g_rel;                    // master release counter

__device__ __forceinline__ unsigned f2tf32(float f) {
    unsigned r;
    asm("cvt.rna.tf32.f32 %0, %1;" : "=r"(r) : "f"(f));
    return r;
}

__device__ __forceinline__ void mma_tf32(float* d, const unsigned* a, const unsigned* b) {
    asm volatile(
        "mma.sync.aligned.m16n8k8.row.col.f32.tf32.tf32.f32 "
        "{%0,%1,%2,%3}, {%4,%5,%6,%7}, {%8,%9}, {%0,%1,%2,%3};"
        : "+f"(d[0]), "+f"(d[1]), "+f"(d[2]), "+f"(d[3])
        : "r"(a[0]), "r"(a[1]), "r"(a[2]), "r"(a[3]), "r"(b[0]), "r"(b[1]));
}

// ---------------------------------------------------------------------------
__global__ void init_kernel(const float* __restrict__ init_states,
                            const float* __restrict__ bi, const float* __restrict__ bf,
                            const float* __restrict__ bc, const float* __restrict__ bo)
{
    int i = blockIdx.x * blockDim.x + threadIdx.x;
    if (i < Bdim*Hdim) {
        int b = i >> 9, j = i & 511;
        g_h[0][b*HROW + j] = init_states[i];    // h0 into padded layout
    }
    if (i < NG) {
        int gate = i >> 9, c = i & 511;
        const float* b = (gate==0) ? bi : (gate==1) ? bf : (gate==2) ? bc : bo;
        g_bias[i] = b[c];
    }
    if (i < 128) g_flag[i] = 0u;
    if (i == 0)  g_rel = 0u;
}

// ---------------------------------------------------------------------------
__global__ __launch_bounds__(256) void prep_x_kernel(const float* __restrict__ X) {
    int idx = blockIdx.x * blockDim.x + threadIdx.x;
    int m  = idx >> 7;
    int k4 = idx & 127;
    int b = m & 31, t = m >> 5;
    float4 v = *(const float4*)(X + ((size_t)b * Tdim + t) * DIdim + k4*4);
    uint4 o;
    o.x = f2tf32(v.x); o.y = f2tf32(v.y); o.z = f2tf32(v.z); o.w = f2tf32(v.w);
    *(uint4*)(g_A + (size_t)m * DIdim + k4*4) = o;
}

__global__ __launch_bounds__(256) void prep_w_kernel(
    const float* __restrict__ Wi, const float* __restrict__ Wf,
    const float* __restrict__ Wc, const float* __restrict__ Wo)
{
    int idx = blockIdx.x * blockDim.x + threadIdx.x;
    int gate = idx >> 16;
    int rem  = idx & 65535;
    int k  = rem >> 7;
    int c4 = rem & 127;
    const float* W = (gate==0) ? Wi : (gate==1) ? Wf : (gate==2) ? Wc : Wo;
    float4 v = *(const float4*)(W + (size_t)k * Hdim + c4*4);
    uint4 o;
    o.x = f2tf32(v.x); o.y = f2tf32(v.y); o.z = f2tf32(v.z); o.w = f2tf32(v.w);
    *(uint4*)(g_Wt + (size_t)k * NG + gate*512 + c4*4) = o;
}

// U fused + block-interleaved: g_Ut[k][ (j>>2)*16 + gate*4 + (j&3) ]
__global__ __launch_bounds__(256) void prep_u_kernel(
    const float* __restrict__ Ui, const float* __restrict__ Uf,
    const float* __restrict__ Uc, const float* __restrict__ Uo)
{
    int idx = blockIdx.x * blockDim.x + threadIdx.x;
    int gate = idx >> 16;
    int rem  = idx & 65535;
    int k  = rem >> 7;
    int jq = rem & 127;
    const float* U = (gate==0) ? Ui : (gate==1) ? Uf : (gate==2) ? Uc : Uo;
    float4 v = *(const float4*)(U + (size_t)k * Hdim + jq*4);
    uint4 o;
    o.x = f2tf32(v.x); o.y = f2tf32(v.y); o.z = f2tf32(v.z); o.w = f2tf32(v.w);
    *(uint4*)(g_Ut + (size_t)k * NG + jq*16 + gate*4) = o;
}

// ---------------------------------------------------------------------------
// xw GEMM (unchanged, verified): C[32768,2048] = A @ Wt + bias -> g_G
// ---------------------------------------------------------------------------
#define AS_PAD 36
#define BS_PAD 68

__global__ __launch_bounds__(256) void xw_mma_kernel() {
    __shared__ unsigned As[128 * AS_PAD];
    __shared__ unsigned Bs[32 * BS_PAD];

    const int tid = threadIdx.x;
    const int wid = tid >> 5;
    const int lane = tid & 31;
    const int gid = lane >> 2;
    const int tig = lane & 3;

    const int warp_m = (wid & 3) * 32;
    const int warp_n = (wid >> 2) * 32;

    const int mbase = blockIdx.x * 128;
    const int nbase = blockIdx.y * 64;

    float acc[2][4][4];
    #pragma unroll
    for (int mt = 0; mt < 2; mt++)
        #pragma unroll
        for (int nt = 0; nt < 4; nt++)
            #pragma unroll
            for (int r = 0; r < 4; r++) acc[mt][nt][r] = 0.f;

    for (int k0 = 0; k0 < DIdim; k0 += 32) {
        #pragma unroll
        for (int r = 0; r < 4; r++) {
            int i = tid + r * 256;
            int row = i >> 3;
            int k4 = (i & 7) * 4;
            uint4 v = *(const uint4*)(g_A + (size_t)(mbase + row) * DIdim + k0 + k4);
            *(uint4*)&As[row * AS_PAD + k4] = v;
        }
        #pragma unroll
        for (int r = 0; r < 2; r++) {
            int i = tid + r * 256;
            int krow = i >> 4;
            int n4 = (i & 15) * 4;
            uint4 v = *(const uint4*)(g_Wt + (size_t)(k0 + krow) * NG + nbase + n4);
            *(uint4*)&Bs[krow * BS_PAD + n4] = v;
        }
        __syncthreads();

        #pragma unroll
        for (int ks = 0; ks < 4; ks++) {
            const int k8 = ks * 8;
            unsigned af[2][4];
            #pragma unroll
            for (int mt = 0; mt < 2; mt++) {
                int row = warp_m + mt*16 + gid;
                af[mt][0] = As[(row    ) * AS_PAD + k8 + tig    ];
                af[mt][1] = As[(row + 8) * AS_PAD + k8 + tig    ];
                af[mt][2] = As[(row    ) * AS_PAD + k8 + tig + 4];
                af[mt][3] = As[(row + 8) * AS_PAD + k8 + tig + 4];
            }
            unsigned bf2[4][2];
            #pragma unroll
            for (int nt = 0; nt < 4; nt++) {
                int col = warp_n + nt*8 + gid;
                bf2[nt][0] = Bs[(k8 + tig    ) * BS_PAD + col];
                bf2[nt][1] = Bs[(k8 + tig + 4) * BS_PAD + col];
            }
            #pragma unroll
            for (int mt = 0; mt < 2; mt++)
                #pragma unroll
                for (int nt = 0; nt < 4; nt++)
                    mma_tf32(acc[mt][nt], af[mt], bf2[nt]);
        }
        __syncthreads();
    }

    #pragma unroll
    for (int mt = 0; mt < 2; mt++) {
        #pragma unroll
        for (int nt = 0; nt < 4; nt++) {
            int col = nbase + warp_n + nt*8 + 2*tig;
            float b0 = g_bias[col];
            float b1 = g_bias[col + 1];
            int row0 = mbase + warp_m + mt*16 + gid;
            float2 o0 = make_float2(acc[mt][nt][0] + b0, acc[mt][nt][1] + b1);
            float2 o1 = make_float2(acc[mt][nt][2] + b0, acc[mt][nt][3] + b1);
            *(float2*)(g_G + (size_t)row0 * NG + col)       = o0;
            *(float2*)(g_G + (size_t)(row0 + 8) * NG + col) = o1;
        }
    }
}

// ---------------------------------------------------------------------------
// Persistent tensor-core recurrence. 128 CTAs x 256 threads, clusters of 4.
// h all-gather via cooperative-sliced TMA bulk MULTICAST (unchanged).
// NEW: two-level flag barrier (distinct-address flags + master release)
// replaces the contended single-address atomic barrier.
// ---------------------------------------------------------------------------
#define SH_H 0
#define SH_P 16512                       // floats (== 32*516)
#define SH_TOTAL (SH_P + 8*290)          // floats
#define SMEM_BYTES (SH_TOTAL*4 + 16)     // + mbarrier

__global__ __launch_bounds__(256,1) __cluster_dims__(4,1,1)
void lstm_kernel(const float* __restrict__ init_states,
                 float* __restrict__ out)
{
    extern __shared__ __align__(16) float smf[];

    const int tid  = threadIdx.x;
    const int w    = tid >> 5;
    const int lane = tid & 31;
    const int gid  = lane >> 2;
    const int tig  = lane & 3;
    const int kh   = w & 3;        // k-quarter (128 k each)
    const int mt   = w >> 2;       // m-tile (16 batches each)
    const int jb   = blockIdx.x * 4;
    const int kbase = kh * 128;
    const bool is_master = (blockIdx.x == 0);

    unsigned smem_u32;
    asm("{ .reg .u64 t0; cvta.to.shared.u64 t0, %1; cvt.u32.u64 %0, t0; }"
        : "=r"(smem_u32) : "l"(smf));
    const unsigned mbar = smem_u32 + SH_TOTAL*4;

    unsigned rank;
    asm("mov.u32 %0, %%cluster_ctarank;" : "=r"(rank));

    // --- preload U fragments into registers (once): ub[nt][ks][2] ---
    unsigned ub[2][16][2];
    {
        #pragma unroll
        for (int nt = 0; nt < 2; nt++) {
            const unsigned* Ucol = g_Ut + (size_t)kbase * NG + blockIdx.x*16 + nt*8 + gid;
            #pragma unroll
            for (int ks = 0; ks < 16; ks++) {
                ub[nt][ks][0] = Ucol[(size_t)(ks*8 + tig    ) * NG];
                ub[nt][ks][1] = Ucol[(size_t)(ks*8 + tig + 4) * NG];
            }
        }
    }

    // owner mapping (tid < 128): one (batch, jj) cell each
    const int o_b  = tid >> 2;     // 0..31
    const int o_jj = tid & 3;
    const int o_mt = o_b >> 4;
    const int o_row = o_b & 15;
    float cstate = 0.f;
    if (tid < 128) cstate = init_states[Bdim*Hdim + o_b*Hdim + jb + o_jj];

    // mbarrier init + cluster sync (peers' multicast needs my mbar live)
    if (tid == 0) {
        asm volatile("mbarrier.init.shared.b64 [%0], 1;" :: "r"(mbar) : "memory");
    }
    __syncthreads();
    asm volatile("barrier.cluster.arrive.aligned;" ::: "memory");
    asm volatile("barrier.cluster.wait.aligned;" ::: "memory");

    float hn = 0.f;   // carried for deferred out-store

    for (int t = 0; t < Tdim; t++) {
        // prefetch G (DRAM; consumed after mma+reduce)
        float pg0=0.f, pg1=0.f, pg2=0.f, pg3=0.f;
        if (tid < 128) {
            const float* gr = g_G + ((size_t)t * Bdim + o_b) * NG + jb + o_jj;
            pg0 = __ldcg(gr);
            pg1 = __ldcg(gr + 512);
            pg2 = __ldcg(gr + 1024);
            pg3 = __ldcg(gr + 1536);
        }

        // ---- cooperative-sliced TMA multicast of h ----
        if (tid == 0) {
            asm volatile("mbarrier.arrive.expect_tx.shared.b64 _, [%0], %1;"
                         :: "r"(mbar), "r"(H_BYTES) : "memory");
            const char* src = (const char*)(g_h[t & 1]) + rank * H_SLICE_BYTES;
            unsigned dst = smem_u32 + rank * H_SLICE_BYTES;
            asm volatile(
                "cp.async.bulk.shared::cluster.global.mbarrier::complete_tx::bytes.multicast::cluster "
                "[%0], [%1], %2, [%3], %4;"
                :: "r"(dst), "l"(src), "r"(H_SLICE_BYTES), "r"(mbar),
                   "h"((unsigned short)0xF) : "memory");
        }
        // wait for full 64KB (4 slices, incl. peers')
        {
            unsigned parity = t & 1;
            asm volatile(
                "{\n\t.reg .pred P;\n"
                "W%=:\n\t"
                "mbarrier.try_wait.parity.acquire.cta.shared::cta.b64 P, [%0], %1, 0x989680;\n\t"
                "@P bra D%=;\n\t"
                "bra W%=;\n"
                "D%=:\n\t}"
                :: "r"(mbar), "r"(parity) : "memory");
        }

        // mma: warp tile m16 x n16, K=128; hi/lo SEPARATE chains (depth 16)
        float acch[2][4], accl[2][4];
        #pragma unroll
        for (int nt = 0; nt < 2; nt++)
            #pragma unroll
            for (int r = 0; r < 4; r++) { acch[nt][r] = 0.f; accl[nt][r] = 0.f; }
        {
            const int row = mt*16 + gid;
            const float* hs = &smf[SH_H + row*HROW + kbase + tig];
            #pragma unroll
            for (int ks = 0; ks < 16; ks++) {
                float h0 = hs[ks*8];
                float h1 = hs[ks*8 + 8*HROW];
                float h2 = hs[ks*8 + 4];
                float h3 = hs[ks*8 + 8*HROW + 4];
                unsigned ahi[4], alo[4];
                ahi[0] = f2tf32(h0); alo[0] = f2tf32(h0 - __uint_as_float(ahi[0]));
                ahi[1] = f2tf32(h1); alo[1] = f2tf32(h1 - __uint_as_float(ahi[1]));
                ahi[2] = f2tf32(h2); alo[2] = f2tf32(h2 - __uint_as_float(ahi[2]));
                ahi[3] = f2tf32(h3); alo[3] = f2tf32(h3 - __uint_as_float(ahi[3]));
                mma_tf32(acch[0], ahi, ub[0][ks]);
                mma_tf32(acch[1], ahi, ub[1][ks]);
                mma_tf32(accl[0], alo, ub[0][ks]);
                mma_tf32(accl[1], alo, ub[1][ks]);
            }
        }
        __syncthreads();   // all lanes done reading smem h (TMA next step rewrites)

        // stash merged partials: pbuf[w][row16][n16] (row stride 18, blk 290)
        {
            float* pb = &smf[SH_P + w*290];
            #pragma unroll
            for (int nt = 0; nt < 2; nt++) {
                *(float2*)&pb[ gid     *18 + nt*8 + 2*tig] =
                    make_float2(acch[nt][0] + accl[nt][0], acch[nt][1] + accl[nt][1]);
                *(float2*)&pb[(gid + 8)*18 + nt*8 + 2*tig] =
                    make_float2(acch[nt][2] + accl[nt][2], acch[nt][3] + accl[nt][3]);
            }
        }
        __syncthreads();

        // owners: 4-way k-reduce + G + LSTM cell; write h (padded layout)
        if (tid < 128) {
            const float* pb = &smf[SH_P + (o_mt*4)*290 + o_row*18 + o_jj];
            float z0 = pg0, z1 = pg1, z2 = pg2, z3 = pg3;
            #pragma unroll
            for (int q = 0; q < 4; q++) {
                const float* r = pb + q*290;
                z0 += r[0];    // i
                z1 += r[4];    // f
                z2 += r[8];    // g
                z3 += r[12];   // o
            }
            float iv = 1.f / (1.f + __expf(-z0));
            float fv = 1.f / (1.f + __expf(-z1));
            float gv = tanhf(z2);
            float ov = 1.f / (1.f + __expf(-z3));
            cstate = fv * cstate + iv * gv;
            hn = ov * tanhf(cstate);
            g_h[(t+1) & 1][o_b*HROW + jb + o_jj] = hn;
        }
        __syncthreads();

        // ---- two-level flag barrier ----
        // arrival: one fence + one relaxed store per CTA (distinct addresses)
        if (tid == 0) {
            asm volatile("membar.gl;" ::: "memory");
            asm volatile("st.relaxed.gpu.global.u32 [%0], %1;"
                         :: "l"(&g_flag[blockIdx.x]), "r"((unsigned)(t+1)) : "memory");
        }

        // deferred out store overlaps the barrier wait
        if (tid < 128) {
            out[((size_t)o_b * Tdim + t) * Hdim + jb + o_jj] = hn;
        }

        // master aggregates 128 flags, then releases
        if (is_master) {
            if (tid < 128) {
                unsigned v;
                do {
                    asm volatile("ld.acquire.gpu.global.u32 %0, [%1];"
                                 : "=r"(v) : "l"(&g_flag[tid]) : "memory");
                } while (v < (unsigned)(t+1));
            }
            __syncthreads();
            if (tid == 0) {
                asm volatile("st.release.gpu.global.u32 [%0], %1;"
                             :: "l"(&g_rel), "r"((unsigned)(t+1)) : "memory");
            }
        }

        // all CTAs wait for release
        if (tid == 0) {
            unsigned v;
            do {
                asm volatile("ld.acquire.gpu.global.u32 %0, [%1];"
                             : "=r"(v) : "l"(&g_rel) : "memory");
            } while (v < (unsigned)(t+1));
        }
        __syncthreads();
    }

    asm volatile("barrier.cluster.arrive.aligned;" ::: "memory");
    asm volatile("barrier.cluster.wait.aligned;" ::: "memory");
}

// ---------------------------------------------------------------------------
extern "C" void kernel_launch(void* const* d_in, const int* in_sizes, int n_in,
                              void* d_out, int out_size) {
    const float* X           = (const float*)d_in[0];
    const float* init_states = (const float*)d_in[1];
    const float* Wi = (const float*)d_in[2];
    const float* Ui = (const float*)d_in[3];
    const float* bi = (const float*)d_in[4];
    const float* Wf = (const float*)d_in[5];
    const float* Uf = (const float*)d_in[6];
    const float* bf = (const float*)d_in[7];
    const float* Wc = (const float*)d_in[8];
    const float* Uc = (const float*)d_in[9];
    const float* bc = (const float*)d_in[10];
    const float* Wo = (const float*)d_in[11];
    const float* Uo = (const float*)d_in[12];
    const float* bo = (const float*)d_in[13];
    float* out = (float*)d_out;

    cudaFuncSetAttribute(lstm_kernel, cudaFuncAttributeMaxDynamicSharedMemorySize,
                         SMEM_BYTES);

    init_kernel<<<(Bdim*Hdim + 255)/256, 256>>>(init_states, bi, bf, bc, bo);

    prep_x_kernel<<<(Tdim*Bdim*DIdim/4 + 255)/256, 256>>>(X);
    prep_w_kernel<<<(DIdim*NG/4 + 255)/256, 256>>>(Wi, Wf, Wc, Wo);
    prep_u_kernel<<<(Hdim*NG/4 + 255)/256, 256>>>(Ui, Uf, Uc, Uo);

    dim3 gemm_grid((Bdim*Tdim)/128, NG/64);
    xw_mma_kernel<<<gemm_grid, 256>>>();

    lstm_kernel<<<128, 256, SMEM_BYTES>>>(init_states, out);
}

// round 8
// speedup vs baseline: 1.1985x; 1.1985x over previous
#include <cuda_runtime.h>
#include <math.h>

#define Bdim 32
#define Tdim 1024
#define DIdim 512
#define Hdim 512
#define NG (4*Hdim)

#define HROW 516                       // padded h row (floats)
#define H_SLICE_BYTES 16512u           // 8 rows * 516 * 4
#define H_BYTES 66048u                 // 32 rows * 516 * 4

// Scratch (device globals)
__device__ float    g_G[Tdim*Bdim*NG];        // [t][b][gate*512+j] = x@W + bias
__device__ unsigned g_A[Tdim*Bdim*DIdim];     // tf32(X) gathered, row m=t*32+b
__device__ unsigned g_Wt[DIdim*NG];           // tf32(W) fused [k][gate*512+c]
__device__ unsigned g_Ut[Hdim*NG];            // tf32(U) fused block-interleaved
__device__ float    g_bias[NG];
__device__ __align__(16) float g_h[2][32*HROW];  // fp32 h, PADDED layout, double-buffered
__device__ unsigned int g_bar;                // grid barrier counter

__device__ __forceinline__ unsigned f2tf32(float f) {
    unsigned r;
    asm("cvt.rna.tf32.f32 %0, %1;" : "=r"(r) : "f"(f));
    return r;
}

__device__ __forceinline__ void mma_tf32(float* d, const unsigned* a, const unsigned* b) {
    asm volatile(
        "mma.sync.aligned.m16n8k8.row.col.f32.tf32.tf32.f32 "
        "{%0,%1,%2,%3}, {%4,%5,%6,%7}, {%8,%9}, {%0,%1,%2,%3};"
        : "+f"(d[0]), "+f"(d[1]), "+f"(d[2]), "+f"(d[3])
        : "r"(a[0]), "r"(a[1]), "r"(a[2]), "r"(a[3]), "r"(b[0]), "r"(b[1]));
}

// ---------------------------------------------------------------------------
__global__ void init_kernel(const float* __restrict__ init_states,
                            const float* __restrict__ bi, const float* __restrict__ bf,
                            const float* __restrict__ bc, const float* __restrict__ bo)
{
    int i = blockIdx.x * blockDim.x + threadIdx.x;
    if (i < Bdim*Hdim) {
        int b = i >> 9, j = i & 511;
        g_h[0][b*HROW + j] = init_states[i];    // h0 into padded layout
    }
    if (i < NG) {
        int gate = i >> 9, c = i & 511;
        const float* b = (gate==0) ? bi : (gate==1) ? bf : (gate==2) ? bc : bo;
        g_bias[i] = b[c];
    }
    if (i == 0) g_bar = 0u;
}

// ---------------------------------------------------------------------------
__global__ __launch_bounds__(256) void prep_x_kernel(const float* __restrict__ X) {
    int idx = blockIdx.x * blockDim.x + threadIdx.x;
    int m  = idx >> 7;
    int k4 = idx & 127;
    int b = m & 31, t = m >> 5;
    float4 v = *(const float4*)(X + ((size_t)b * Tdim + t) * DIdim + k4*4);
    uint4 o;
    o.x = f2tf32(v.x); o.y = f2tf32(v.y); o.z = f2tf32(v.z); o.w = f2tf32(v.w);
    *(uint4*)(g_A + (size_t)m * DIdim + k4*4) = o;
}

__global__ __launch_bounds__(256) void prep_w_kernel(
    const float* __restrict__ Wi, const float* __restrict__ Wf,
    const float* __restrict__ Wc, const float* __restrict__ Wo)
{
    int idx = blockIdx.x * blockDim.x + threadIdx.x;
    int gate = idx >> 16;
    int rem  = idx & 65535;
    int k  = rem >> 7;
    int c4 = rem & 127;
    const float* W = (gate==0) ? Wi : (gate==1) ? Wf : (gate==2) ? Wc : Wo;
    float4 v = *(const float4*)(W + (size_t)k * Hdim + c4*4);
    uint4 o;
    o.x = f2tf32(v.x); o.y = f2tf32(v.y); o.z = f2tf32(v.z); o.w = f2tf32(v.w);
    *(uint4*)(g_Wt + (size_t)k * NG + gate*512 + c4*4) = o;
}

// U fused + block-interleaved: g_Ut[k][ (j>>2)*16 + gate*4 + (j&3) ]
__global__ __launch_bounds__(256) void prep_u_kernel(
    const float* __restrict__ Ui, const float* __restrict__ Uf,
    const float* __restrict__ Uc, const float* __restrict__ Uo)
{
    int idx = blockIdx.x * blockDim.x + threadIdx.x;
    int gate = idx >> 16;
    int rem  = idx & 65535;
    int k  = rem >> 7;
    int jq = rem & 127;
    const float* U = (gate==0) ? Ui : (gate==1) ? Uf : (gate==2) ? Uc : Uo;
    float4 v = *(const float4*)(U + (size_t)k * Hdim + jq*4);
    uint4 o;
    o.x = f2tf32(v.x); o.y = f2tf32(v.y); o.z = f2tf32(v.z); o.w = f2tf32(v.w);
    *(uint4*)(g_Ut + (size_t)k * NG + jq*16 + gate*4) = o;
}

// ---------------------------------------------------------------------------
// xw GEMM (unchanged, verified): C[32768,2048] = A @ Wt + bias -> g_G
// ---------------------------------------------------------------------------
#define AS_PAD 36
#define BS_PAD 68

__global__ __launch_bounds__(256) void xw_mma_kernel() {
    __shared__ unsigned As[128 * AS_PAD];
    __shared__ unsigned Bs[32 * BS_PAD];

    const int tid = threadIdx.x;
    const int wid = tid >> 5;
    const int lane = tid & 31;
    const int gid = lane >> 2;
    const int tig = lane & 3;

    const int warp_m = (wid & 3) * 32;
    const int warp_n = (wid >> 2) * 32;

    const int mbase = blockIdx.x * 128;
    const int nbase = blockIdx.y * 64;

    float acc[2][4][4];
    #pragma unroll
    for (int mt = 0; mt < 2; mt++)
        #pragma unroll
        for (int nt = 0; nt < 4; nt++)
            #pragma unroll
            for (int r = 0; r < 4; r++) acc[mt][nt][r] = 0.f;

    for (int k0 = 0; k0 < DIdim; k0 += 32) {
        #pragma unroll
        for (int r = 0; r < 4; r++) {
            int i = tid + r * 256;
            int row = i >> 3;
            int k4 = (i & 7) * 4;
            uint4 v = *(const uint4*)(g_A + (size_t)(mbase + row) * DIdim + k0 + k4);
            *(uint4*)&As[row * AS_PAD + k4] = v;
        }
        #pragma unroll
        for (int r = 0; r < 2; r++) {
            int i = tid + r * 256;
            int krow = i >> 4;
            int n4 = (i & 15) * 4;
            uint4 v = *(const uint4*)(g_Wt + (size_t)(k0 + krow) * NG + nbase + n4);
            *(uint4*)&Bs[krow * BS_PAD + n4] = v;
        }
        __syncthreads();

        #pragma unroll
        for (int ks = 0; ks < 4; ks++) {
            const int k8 = ks * 8;
            unsigned af[2][4];
            #pragma unroll
            for (int mt = 0; mt < 2; mt++) {
                int row = warp_m + mt*16 + gid;
                af[mt][0] = As[(row    ) * AS_PAD + k8 + tig    ];
                af[mt][1] = As[(row + 8) * AS_PAD + k8 + tig    ];
                af[mt][2] = As[(row    ) * AS_PAD + k8 + tig + 4];
                af[mt][3] = As[(row + 8) * AS_PAD + k8 + tig + 4];
            }
            unsigned bf2[4][2];
            #pragma unroll
            for (int nt = 0; nt < 4; nt++) {
                int col = warp_n + nt*8 + gid;
                bf2[nt][0] = Bs[(k8 + tig    ) * BS_PAD + col];
                bf2[nt][1] = Bs[(k8 + tig + 4) * BS_PAD + col];
            }
            #pragma unroll
            for (int mt = 0; mt < 2; mt++)
                #pragma unroll
                for (int nt = 0; nt < 4; nt++)
                    mma_tf32(acc[mt][nt], af[mt], bf2[nt]);
        }
        __syncthreads();
    }

    #pragma unroll
    for (int mt = 0; mt < 2; mt++) {
        #pragma unroll
        for (int nt = 0; nt < 4; nt++) {
            int col = nbase + warp_n + nt*8 + 2*tig;
            float b0 = g_bias[col];
            float b1 = g_bias[col + 1];
            int row0 = mbase + warp_m + mt*16 + gid;
            float2 o0 = make_float2(acc[mt][nt][0] + b0, acc[mt][nt][1] + b1);
            float2 o1 = make_float2(acc[mt][nt][2] + b0, acc[mt][nt][3] + b1);
            *(float2*)(g_G + (size_t)row0 * NG + col)       = o0;
            *(float2*)(g_G + (size_t)(row0 + 8) * NG + col) = o1;
        }
    }
}

// ---------------------------------------------------------------------------
// Persistent tensor-core recurrence. 128 CTAs x 256 threads, clusters of 4.
// h all-gather via cooperative-sliced TMA bulk MULTICAST (verified round 6).
// Barrier: single-atomic arrive (cheap: ~0.854 cyc/arrival at L2) with ONE
// gpu-scope fence per CTA (CG grid.sync pattern) — reverts round 7's
// two-level flag barrier (it added 2 serialized L2 round-trips, -817us).
// ---------------------------------------------------------------------------
#define SH_H 0
#define SH_P 16512                       // floats (== 32*516)
#define SH_TOTAL (SH_P + 8*290)          // floats
#define SMEM_BYTES (SH_TOTAL*4 + 16)     // + mbarrier

__global__ __launch_bounds__(256,1) __cluster_dims__(4,1,1)
void lstm_kernel(const float* __restrict__ init_states,
                 float* __restrict__ out)
{
    extern __shared__ __align__(16) float smf[];

    const int tid  = threadIdx.x;
    const int w    = tid >> 5;
    const int lane = tid & 31;
    const int gid  = lane >> 2;
    const int tig  = lane & 3;
    const int kh   = w & 3;        // k-quarter (128 k each)
    const int mt   = w >> 2;       // m-tile (16 batches each)
    const int jb   = blockIdx.x * 4;
    const int kbase = kh * 128;

    unsigned smem_u32;
    asm("{ .reg .u64 t0; cvta.to.shared.u64 t0, %1; cvt.u32.u64 %0, t0; }"
        : "=r"(smem_u32) : "l"(smf));
    const unsigned mbar = smem_u32 + SH_TOTAL*4;

    unsigned rank;
    asm("mov.u32 %0, %%cluster_ctarank;" : "=r"(rank));

    // --- preload U fragments into registers (once): ub[nt][ks][2] ---
    unsigned ub[2][16][2];
    {
        #pragma unroll
        for (int nt = 0; nt < 2; nt++) {
            const unsigned* Ucol = g_Ut + (size_t)kbase * NG + blockIdx.x*16 + nt*8 + gid;
            #pragma unroll
            for (int ks = 0; ks < 16; ks++) {
                ub[nt][ks][0] = Ucol[(size_t)(ks*8 + tig    ) * NG];
                ub[nt][ks][1] = Ucol[(size_t)(ks*8 + tig + 4) * NG];
            }
        }
    }

    // owner mapping (tid < 128): one (batch, jj) cell each
    const int o_b  = tid >> 2;     // 0..31
    const int o_jj = tid & 3;
    const int o_mt = o_b >> 4;
    const int o_row = o_b & 15;
    float cstate = 0.f;
    if (tid < 128) cstate = init_states[Bdim*Hdim + o_b*Hdim + jb + o_jj];

    // mbarrier init + cluster sync (peers' multicast needs my mbar live)
    if (tid == 0) {
        asm volatile("mbarrier.init.shared.b64 [%0], 1;" :: "r"(mbar) : "memory");
    }
    __syncthreads();
    asm volatile("barrier.cluster.arrive.aligned;" ::: "memory");
    asm volatile("barrier.cluster.wait.aligned;" ::: "memory");

    float hn = 0.f;   // carried for deferred out-store

    for (int t = 0; t < Tdim; t++) {
        // prefetch G (DRAM; consumed after mma+reduce)
        float pg0=0.f, pg1=0.f, pg2=0.f, pg3=0.f;
        if (tid < 128) {
            const float* gr = g_G + ((size_t)t * Bdim + o_b) * NG + jb + o_jj;
            pg0 = __ldcg(gr);
            pg1 = __ldcg(gr + 512);
            pg2 = __ldcg(gr + 1024);
            pg3 = __ldcg(gr + 1536);
        }

        // ---- cooperative-sliced TMA multicast of h ----
        if (tid == 0) {
            asm volatile("mbarrier.arrive.expect_tx.shared.b64 _, [%0], %1;"
                         :: "r"(mbar), "r"(H_BYTES) : "memory");
            const char* src = (const char*)(g_h[t & 1]) + rank * H_SLICE_BYTES;
            unsigned dst = smem_u32 + rank * H_SLICE_BYTES;
            asm volatile(
                "cp.async.bulk.shared::cluster.global.mbarrier::complete_tx::bytes.multicast::cluster "
                "[%0], [%1], %2, [%3], %4;"
                :: "r"(dst), "l"(src), "r"(H_SLICE_BYTES), "r"(mbar),
                   "h"((unsigned short)0xF) : "memory");
        }
        // wait for full 64KB (4 slices, incl. peers')
        {
            unsigned parity = t & 1;
            asm volatile(
                "{\n\t.reg .pred P;\n"
                "W%=:\n\t"
                "mbarrier.try_wait.parity.acquire.cta.shared::cta.b64 P, [%0], %1, 0x989680;\n\t"
                "@P bra D%=;\n\t"
                "bra W%=;\n"
                "D%=:\n\t}"
                :: "r"(mbar), "r"(parity) : "memory");
        }

        // mma: warp tile m16 x n16, K=128; hi/lo SEPARATE chains (depth 16)
        float acch[2][4], accl[2][4];
        #pragma unroll
        for (int nt = 0; nt < 2; nt++)
            #pragma unroll
            for (int r = 0; r < 4; r++) { acch[nt][r] = 0.f; accl[nt][r] = 0.f; }
        {
            const int row = mt*16 + gid;
            const float* hs = &smf[SH_H + row*HROW + kbase + tig];
            #pragma unroll
            for (int ks = 0; ks < 16; ks++) {
                float h0 = hs[ks*8];
                float h1 = hs[ks*8 + 8*HROW];
                float h2 = hs[ks*8 + 4];
                float h3 = hs[ks*8 + 8*HROW + 4];
                unsigned ahi[4], alo[4];
                ahi[0] = f2tf32(h0); alo[0] = f2tf32(h0 - __uint_as_float(ahi[0]));
                ahi[1] = f2tf32(h1); alo[1] = f2tf32(h1 - __uint_as_float(ahi[1]));
                ahi[2] = f2tf32(h2); alo[2] = f2tf32(h2 - __uint_as_float(ahi[2]));
                ahi[3] = f2tf32(h3); alo[3] = f2tf32(h3 - __uint_as_float(ahi[3]));
                mma_tf32(acch[0], ahi, ub[0][ks]);
                mma_tf32(acch[1], ahi, ub[1][ks]);
                mma_tf32(accl[0], alo, ub[0][ks]);
                mma_tf32(accl[1], alo, ub[1][ks]);
            }
        }
        __syncthreads();   // all lanes done reading smem h (TMA next step rewrites)

        // stash merged partials: pbuf[w][row16][n16] (row stride 18, blk 290)
        {
            float* pb = &smf[SH_P + w*290];
            #pragma unroll
            for (int nt = 0; nt < 2; nt++) {
                *(float2*)&pb[ gid     *18 + nt*8 + 2*tig] =
                    make_float2(acch[nt][0] + accl[nt][0], acch[nt][1] + accl[nt][1]);
                *(float2*)&pb[(gid + 8)*18 + nt*8 + 2*tig] =
                    make_float2(acch[nt][2] + accl[nt][2], acch[nt][3] + accl[nt][3]);
            }
        }
        __syncthreads();

        // owners: 4-way k-reduce + G + LSTM cell; write h (padded layout)
        if (tid < 128) {
            const float* pb = &smf[SH_P + (o_mt*4)*290 + o_row*18 + o_jj];
            float z0 = pg0, z1 = pg1, z2 = pg2, z3 = pg3;
            #pragma unroll
            for (int q = 0; q < 4; q++) {
                const float* r = pb + q*290;
                z0 += r[0];    // i
                z1 += r[4];    // f
                z2 += r[8];    // g
                z3 += r[12];   // o
            }
            float iv = 1.f / (1.f + __expf(-z0));
            float fv = 1.f / (1.f + __expf(-z1));
            float gv = tanhf(z2);
            float ov = 1.f / (1.f + __expf(-z3));
            cstate = fv * cstate + iv * gv;
            hn = ov * tanhf(cstate);
            g_h[(t+1) & 1][o_b*HROW + jb + o_jj] = hn;
        }
        __syncthreads();    // all h stores done (CTA scope)

        // ---- grid barrier: ONE fence + one atomic arrive per CTA ----
        if (tid == 0) {
            asm volatile("membar.gl;" ::: "memory");
            atomicAdd(&g_bar, 1u);
        }

        // deferred out store overlaps the barrier wait
        if (tid < 128) {
            out[((size_t)o_b * Tdim + t) * Hdim + jb + o_jj] = hn;
        }

        if (tid == 0) {
            unsigned target = (unsigned)gridDim.x * (unsigned)(t + 1);
            unsigned v;
            do {
                asm volatile("ld.acquire.gpu.global.u32 %0, [%1];"
                             : "=r"(v) : "l"(&g_bar) : "memory");
            } while (v < target);
        }
        __syncthreads();
    }

    asm volatile("barrier.cluster.arrive.aligned;" ::: "memory");
    asm volatile("barrier.cluster.wait.aligned;" ::: "memory");
}

// ---------------------------------------------------------------------------
extern "C" void kernel_launch(void* const* d_in, const int* in_sizes, int n_in,
                              void* d_out, int out_size) {
    const float* X           = (const float*)d_in[0];
    const float* init_states = (const float*)d_in[1];
    const float* Wi = (const float*)d_in[2];
    const float* Ui = (const float*)d_in[3];
    const float* bi = (const float*)d_in[4];
    const float* Wf = (const float*)d_in[5];
    const float* Uf = (const float*)d_in[6];
    const float* bf = (const float*)d_in[7];
    const float* Wc = (const float*)d_in[8];
    const float* Uc = (const float*)d_in[9];
    const float* bc = (const float*)d_in[10];
    const float* Wo = (const float*)d_in[11];
    const float* Uo = (const float*)d_in[12];
    const float* bo = (const float*)d_in[13];
    float* out = (float*)d_out;

    cudaFuncSetAttribute(lstm_kernel, cudaFuncAttributeMaxDynamicSharedMemorySize,
                         SMEM_BYTES);

    init_kernel<<<(Bdim*Hdim + 255)/256, 256>>>(init_states, bi, bf, bc, bo);

    prep_x_kernel<<<(Tdim*Bdim*DIdim/4 + 255)/256, 256>>>(X);
    prep_w_kernel<<<(DIdim*NG/4 + 255)/256, 256>>>(Wi, Wf, Wc, Wo);
    prep_u_kernel<<<(Hdim*NG/4 + 255)/256, 256>>>(Ui, Uf, Uc, Uo);

    dim3 gemm_grid((Bdim*Tdim)/128, NG/64);
    xw_mma_kernel<<<gemm_grid, 256>>>();

    lstm_kernel<<<128, 256, SMEM_BYTES>>>(init_states, out);
}

// round 10
// speedup vs baseline: 1.4968x; 1.2489x over previous
#include <cuda_runtime.h>
#include <math.h>

#define Bdim 32
#define Tdim 1024
#define DIdim 512
#define Hdim 512
#define NG (4*Hdim)

#define HROW 516                       // padded h row (floats)
#define H_SLICE_BYTES 16512u           // 8 rows * 516 * 4
#define H_HALF_BYTES  33024u           // 2 slices (16 rows)

// Scratch (device globals)
__device__ float    g_G[Tdim*Bdim*NG];        // [t][b][gate*512+j] = x@W + bias
__device__ unsigned g_A[Tdim*Bdim*DIdim];     // tf32(X) gathered, row m=t*32+b
__device__ unsigned g_Wt[DIdim*NG];           // tf32(W) fused [k][gate*512+c]
__device__ unsigned g_Ut[Hdim*NG];            // tf32(U) fused block-interleaved
__device__ float    g_bias[NG];
__device__ __align__(16) float g_h[2][32*HROW];  // tf32-valued h, PADDED, double-buffered
__device__ unsigned int g_bar;                // grid barrier counter

__device__ __forceinline__ unsigned f2tf32(float f) {
    unsigned r;
    asm("cvt.rna.tf32.f32 %0, %1;" : "=r"(r) : "f"(f));
    return r;
}

__device__ __forceinline__ void mma_tf32(float* d, const unsigned* a, const unsigned* b) {
    asm volatile(
        "mma.sync.aligned.m16n8k8.row.col.f32.tf32.tf32.f32 "
        "{%0,%1,%2,%3}, {%4,%5,%6,%7}, {%8,%9}, {%0,%1,%2,%3};"
        : "+f"(d[0]), "+f"(d[1]), "+f"(d[2]), "+f"(d[3])
        : "r"(a[0]), "r"(a[1]), "r"(a[2]), "r"(a[3]), "r"(b[0]), "r"(b[1]));
}

__device__ __forceinline__ float tanh_fast(float x) {
    float e = __expf(2.0f * x);
    return 1.0f - __fdividef(2.0f, e + 1.0f);   // inf-safe
}
__device__ __forceinline__ float sigmoid_fast(float x) {
    return __fdividef(1.0f, 1.0f + __expf(-x));
}

// ---------------------------------------------------------------------------
__global__ void init_kernel(const float* __restrict__ init_states,
                            const float* __restrict__ bi, const float* __restrict__ bf,
                            const float* __restrict__ bc, const float* __restrict__ bo)
{
    int i = blockIdx.x * blockDim.x + threadIdx.x;
    if (i < Bdim*Hdim) {
        int b = i >> 9, j = i & 511;
        g_h[0][b*HROW + j] = __uint_as_float(f2tf32(init_states[i]));  // tf32-rounded h0
    }
    if (i < NG) {
        int gate = i >> 9, c = i & 511;
        const float* b = (gate==0) ? bi : (gate==1) ? bf : (gate==2) ? bc : bo;
        g_bias[i] = b[c];
    }
    if (i == 0) g_bar = 0u;
}

// ---------------------------------------------------------------------------
__global__ __launch_bounds__(256) void prep_x_kernel(const float* __restrict__ X) {
    int idx = blockIdx.x * blockDim.x + threadIdx.x;
    int m  = idx >> 7;
    int k4 = idx & 127;
    int b = m & 31, t = m >> 5;
    float4 v = *(const float4*)(X + ((size_t)b * Tdim + t) * DIdim + k4*4);
    uint4 o;
    o.x = f2tf32(v.x); o.y = f2tf32(v.y); o.z = f2tf32(v.z); o.w = f2tf32(v.w);
    *(uint4*)(g_A + (size_t)m * DIdim + k4*4) = o;
}

__global__ __launch_bounds__(256) void prep_w_kernel(
    const float* __restrict__ Wi, const float* __restrict__ Wf,
    const float* __restrict__ Wc, const float* __restrict__ Wo)
{
    int idx = blockIdx.x * blockDim.x + threadIdx.x;
    int gate = idx >> 16;
    int rem  = idx & 65535;
    int k  = rem >> 7;
    int c4 = rem & 127;
    const float* W = (gate==0) ? Wi : (gate==1) ? Wf : (gate==2) ? Wc : Wo;
    float4 v = *(const float4*)(W + (size_t)k * Hdim + c4*4);
    uint4 o;
    o.x = f2tf32(v.x); o.y = f2tf32(v.y); o.z = f2tf32(v.z); o.w = f2tf32(v.w);
    *(uint4*)(g_Wt + (size_t)k * NG + gate*512 + c4*4) = o;
}

// U fused + block-interleaved: g_Ut[k][ (j>>2)*16 + gate*4 + (j&3) ]
__global__ __launch_bounds__(256) void prep_u_kernel(
    const float* __restrict__ Ui, const float* __restrict__ Uf,
    const float* __restrict__ Uc, const float* __restrict__ Uo)
{
    int idx = blockIdx.x * blockDim.x + threadIdx.x;
    int gate = idx >> 16;
    int rem  = idx & 65535;
    int k  = rem >> 7;
    int jq = rem & 127;
    const float* U = (gate==0) ? Ui : (gate==1) ? Uf : (gate==2) ? Uc : Uo;
    float4 v = *(const float4*)(U + (size_t)k * Hdim + jq*4);
    uint4 o;
    o.x = f2tf32(v.x); o.y = f2tf32(v.y); o.z = f2tf32(v.z); o.w = f2tf32(v.w);
    *(uint4*)(g_Ut + (size_t)k * NG + jq*16 + gate*4) = o;
}

// ---------------------------------------------------------------------------
// xw GEMM (unchanged, verified): C[32768,2048] = A @ Wt + bias -> g_G
// ---------------------------------------------------------------------------
#define AS_PAD 36
#define BS_PAD 68

__global__ __launch_bounds__(256) void xw_mma_kernel() {
    __shared__ unsigned As[128 * AS_PAD];
    __shared__ unsigned Bs[32 * BS_PAD];

    const int tid = threadIdx.x;
    const int wid = tid >> 5;
    const int lane = tid & 31;
    const int gid = lane >> 2;
    const int tig = lane & 3;

    const int warp_m = (wid & 3) * 32;
    const int warp_n = (wid >> 2) * 32;

    const int mbase = blockIdx.x * 128;
    const int nbase = blockIdx.y * 64;

    float acc[2][4][4];
    #pragma unroll
    for (int mt = 0; mt < 2; mt++)
        #pragma unroll
        for (int nt = 0; nt < 4; nt++)
            #pragma unroll
            for (int r = 0; r < 4; r++) acc[mt][nt][r] = 0.f;

    for (int k0 = 0; k0 < DIdim; k0 += 32) {
        #pragma unroll
        for (int r = 0; r < 4; r++) {
            int i = tid + r * 256;
            int row = i >> 3;
            int k4 = (i & 7) * 4;
            uint4 v = *(const uint4*)(g_A + (size_t)(mbase + row) * DIdim + k0 + k4);
            *(uint4*)&As[row * AS_PAD + k4] = v;
        }
        #pragma unroll
        for (int r = 0; r < 2; r++) {
            int i = tid + r * 256;
            int krow = i >> 4;
            int n4 = (i & 15) * 4;
            uint4 v = *(const uint4*)(g_Wt + (size_t)(k0 + krow) * NG + nbase + n4);
            *(uint4*)&Bs[krow * BS_PAD + n4] = v;
        }
        __syncthreads();

        #pragma unroll
        for (int ks = 0; ks < 4; ks++) {
            const int k8 = ks * 8;
            unsigned af[2][4];
            #pragma unroll
            for (int mt = 0; mt < 2; mt++) {
                int row = warp_m + mt*16 + gid;
                af[mt][0] = As[(row    ) * AS_PAD + k8 + tig    ];
                af[mt][1] = As[(row + 8) * AS_PAD + k8 + tig    ];
                af[mt][2] = As[(row    ) * AS_PAD + k8 + tig + 4];
                af[mt][3] = As[(row + 8) * AS_PAD + k8 + tig + 4];
            }
            unsigned bf2[4][2];
            #pragma unroll
            for (int nt = 0; nt < 4; nt++) {
                int col = warp_n + nt*8 + gid;
                bf2[nt][0] = Bs[(k8 + tig    ) * BS_PAD + col];
                bf2[nt][1] = Bs[(k8 + tig + 4) * BS_PAD + col];
            }
            #pragma unroll
            for (int mt = 0; mt < 2; mt++)
                #pragma unroll
                for (int nt = 0; nt < 4; nt++)
                    mma_tf32(acc[mt][nt], af[mt], bf2[nt]);
        }
        __syncthreads();
    }

    #pragma unroll
    for (int mt = 0; mt < 2; mt++) {
        #pragma unroll
        for (int nt = 0; nt < 4; nt++) {
            int col = nbase + warp_n + nt*8 + 2*tig;
            float b0 = g_bias[col];
            float b1 = g_bias[col + 1];
            int row0 = mbase + warp_m + mt*16 + gid;
            float2 o0 = make_float2(acc[mt][nt][0] + b0, acc[mt][nt][1] + b1);
            float2 o1 = make_float2(acc[mt][nt][2] + b0, acc[mt][nt][3] + b1);
            *(float2*)(g_G + (size_t)row0 * NG + col)       = o0;
            *(float2*)(g_G + (size_t)(row0 + 8) * NG + col) = o1;
        }
    }
}

// ---------------------------------------------------------------------------
// Persistent tensor-core recurrence. 128 CTAs x 256 threads, clusters of 4.
// h stored as tf32-rounded fp32 (single mma chain — halves tensor work vs
// the hi/lo split). h all-gather via cooperative-sliced TMA multicast, now
// PIPELINED with two mbarriers: slices 0,1 (batches 0-15) -> mbar0,
// slices 2,3 -> mbar1; warps mt=0 wait only mbar0 and start mma early.
// Barrier: round-8 single-atomic (measured-good).
// ---------------------------------------------------------------------------
#define SH_H 0
#define SH_P 16512                       // floats (== 32*516)
#define SH_TOTAL (SH_P + 8*290)          // floats
#define SMEM_BYTES (SH_TOTAL*4 + 16)     // + two mbarriers

__global__ __launch_bounds__(256,1) __cluster_dims__(4,1,1)
void lstm_kernel(const float* __restrict__ init_states,
                 float* __restrict__ out)
{
    extern __shared__ __align__(16) float smf[];

    const int tid  = threadIdx.x;
    const int w    = tid >> 5;
    const int lane = tid & 31;
    const int gid  = lane >> 2;
    const int tig  = lane & 3;
    const int kh   = w & 3;        // k-quarter (128 k each)
    const int mt   = w >> 2;       // m-tile (16 batches each)
    const int jb   = blockIdx.x * 4;
    const int kbase = kh * 128;

    unsigned smem_u32;
    asm("{ .reg .u64 t0; cvta.to.shared.u64 t0, %1; cvt.u32.u64 %0, t0; }"
        : "=r"(smem_u32) : "l"(smf));
    const unsigned mbar0 = smem_u32 + SH_TOTAL*4;
    const unsigned mbar1 = mbar0 + 8;
    const unsigned my_wait_mbar = mt ? mbar1 : mbar0;

    unsigned rank;
    asm("mov.u32 %0, %%cluster_ctarank;" : "=r"(rank));
    const unsigned my_tma_mbar = (rank >> 1) ? mbar1 : mbar0;

    // --- preload U fragments into registers (once): ub[nt][ks][2] ---
    unsigned ub[2][16][2];
    {
        #pragma unroll
        for (int nt = 0; nt < 2; nt++) {
            const unsigned* Ucol = g_Ut + (size_t)kbase * NG + blockIdx.x*16 + nt*8 + gid;
            #pragma unroll
            for (int ks = 0; ks < 16; ks++) {
                ub[nt][ks][0] = Ucol[(size_t)(ks*8 + tig    ) * NG];
                ub[nt][ks][1] = Ucol[(size_t)(ks*8 + tig + 4) * NG];
            }
        }
    }

    // owner mapping (tid < 128): one (batch, jj) cell each
    const int o_b  = tid >> 2;     // 0..31
    const int o_jj = tid & 3;
    const int o_mt = o_b >> 4;
    const int o_row = o_b & 15;
    float cstate = 0.f;
    if (tid < 128) cstate = init_states[Bdim*Hdim + o_b*Hdim + jb + o_jj];

    // mbarrier init + cluster sync (peers' multicast needs my mbars live)
    if (tid == 0) {
        asm volatile("mbarrier.init.shared.b64 [%0], 1;" :: "r"(mbar0) : "memory");
        asm volatile("mbarrier.init.shared.b64 [%0], 1;" :: "r"(mbar1) : "memory");
    }
    __syncthreads();
    asm volatile("barrier.cluster.arrive.aligned;" ::: "memory");
    asm volatile("barrier.cluster.wait.aligned;" ::: "memory");

    float hn = 0.f;   // carried for deferred out-store

    for (int t = 0; t < Tdim; t++) {
        // ---- pipelined cooperative-sliced TMA multicast of h ----
        if (tid == 0) {
            asm volatile("mbarrier.arrive.expect_tx.shared.b64 _, [%0], %1;"
                         :: "r"(mbar0), "r"(H_HALF_BYTES) : "memory");
            asm volatile("mbarrier.arrive.expect_tx.shared.b64 _, [%0], %1;"
                         :: "r"(mbar1), "r"(H_HALF_BYTES) : "memory");
            const char* src = (const char*)(g_h[t & 1]) + rank * H_SLICE_BYTES;
            unsigned dst = smem_u32 + rank * H_SLICE_BYTES;
            asm volatile(
                "cp.async.bulk.shared::cluster.global.mbarrier::complete_tx::bytes.multicast::cluster "
                "[%0], [%1], %2, [%3], %4;"
                :: "r"(dst), "l"(src), "r"(H_SLICE_BYTES), "r"(my_tma_mbar),
                   "h"((unsigned short)0xF) : "memory");
        }

        // prefetch G (DRAM; consumed after mma+reduce) — overlaps TMA
        float pg0=0.f, pg1=0.f, pg2=0.f, pg3=0.f;
        if (tid < 128) {
            const float* gr = g_G + ((size_t)t * Bdim + o_b) * NG + jb + o_jj;
            pg0 = __ldcg(gr);
            pg1 = __ldcg(gr + 512);
            pg2 = __ldcg(gr + 1024);
            pg3 = __ldcg(gr + 1536);
        }

        // wait only for my half (warps mt=0: batches 0-15; mt=1: 16-31)
        {
            unsigned parity = t & 1;
            asm volatile(
                "{\n\t.reg .pred P;\n"
                "W%=:\n\t"
                "mbarrier.try_wait.parity.acquire.cta.shared::cta.b64 P, [%0], %1, 0x989680;\n\t"
                "@P bra D%=;\n\t"
                "bra W%=;\n"
                "D%=:\n\t}"
                :: "r"(my_wait_mbar), "r"(parity) : "memory");
        }

        // mma: warp tile m16 x n16, K=128; SINGLE tf32 chain (h pre-rounded)
        float acc[2][4];
        #pragma unroll
        for (int nt = 0; nt < 2; nt++)
            #pragma unroll
            for (int r = 0; r < 4; r++) acc[nt][r] = 0.f;
        {
            const int row = mt*16 + gid;
            const unsigned* hs = (const unsigned*)&smf[SH_H + row*HROW + kbase + tig];
            #pragma unroll
            for (int ks = 0; ks < 16; ks++) {
                unsigned af[4];
                af[0] = hs[ks*8];
                af[1] = hs[ks*8 + 8*HROW];
                af[2] = hs[ks*8 + 4];
                af[3] = hs[ks*8 + 8*HROW + 4];
                mma_tf32(acc[0], af, ub[0][ks]);
                mma_tf32(acc[1], af, ub[1][ks]);
            }
        }
        __syncthreads();   // all lanes done reading smem h (TMA next step rewrites)

        // stash partials: pbuf[w][row16][n16] (row stride 18, blk 290)
        {
            float* pb = &smf[SH_P + w*290];
            #pragma unroll
            for (int nt = 0; nt < 2; nt++) {
                *(float2*)&pb[ gid     *18 + nt*8 + 2*tig] = make_float2(acc[nt][0], acc[nt][1]);
                *(float2*)&pb[(gid + 8)*18 + nt*8 + 2*tig] = make_float2(acc[nt][2], acc[nt][3]);
            }
        }
        __syncthreads();

        // owners: 4-way k-reduce + G + LSTM cell; write tf32-rounded h
        if (tid < 128) {
            const float* pb = &smf[SH_P + (o_mt*4)*290 + o_row*18 + o_jj];
            float z0 = pg0, z1 = pg1, z2 = pg2, z3 = pg3;
            #pragma unroll
            for (int q = 0; q < 4; q++) {
                const float* r = pb + q*290;
                z0 += r[0];    // i
                z1 += r[4];    // f
                z2 += r[8];    // g
                z3 += r[12];   // o
            }
            float iv = sigmoid_fast(z0);
            float fv = sigmoid_fast(z1);
            float gv = tanh_fast(z2);
            float ov = sigmoid_fast(z3);
            cstate = fv * cstate + iv * gv;
            hn = ov * tanh_fast(cstate);
            g_h[(t+1) & 1][o_b*HROW + jb + o_jj] = __uint_as_float(f2tf32(hn));
        }
        __syncthreads();    // all h stores done (CTA scope)

        // ---- grid barrier: ONE fence + one atomic arrive per CTA ----
        if (tid == 0) {
            asm volatile("membar.gl;" ::: "memory");
            atomicAdd(&g_bar, 1u);
        }

        // deferred out store (full-precision hn) overlaps the barrier wait
        if (tid < 128) {
            out[((size_t)o_b * Tdim + t) * Hdim + jb + o_jj] = hn;
        }

        if (tid == 0) {
            unsigned target = (unsigned)gridDim.x * (unsigned)(t + 1);
            unsigned v;
            do {
                asm volatile("ld.acquire.gpu.global.u32 %0, [%1];"
                             : "=r"(v) : "l"(&g_bar) : "memory");
            } while (v < target);
        }
        __syncthreads();
    }

    asm volatile("barrier.cluster.arrive.aligned;" ::: "memory");
    asm volatile("barrier.cluster.wait.aligned;" ::: "memory");
}

// ---------------------------------------------------------------------------
extern "C" void kernel_launch(void* const* d_in, const int* in_sizes, int n_in,
                              void* d_out, int out_size) {
    const float* X           = (const float*)d_in[0];
    const float* init_states = (const float*)d_in[1];
    const float* Wi = (const float*)d_in[2];
    const float* Ui = (const float*)d_in[3];
    const float* bi = (const float*)d_in[4];
    const float* Wf = (const float*)d_in[5];
    const float* Uf = (const float*)d_in[6];
    const float* bf = (const float*)d_in[7];
    const float* Wc = (const float*)d_in[8];
    const float* Uc = (const float*)d_in[9];
    const float* bc = (const float*)d_in[10];
    const float* Wo = (const float*)d_in[11];
    const float* Uo = (const float*)d_in[12];
    const float* bo = (const float*)d_in[13];
    float* out = (float*)d_out;

    cudaFuncSetAttribute(lstm_kernel, cudaFuncAttributeMaxDynamicSharedMemorySize,
                         SMEM_BYTES);

    init_kernel<<<(Bdim*Hdim + 255)/256, 256>>>(init_states, bi, bf, bc, bo);

    prep_x_kernel<<<(Tdim*Bdim*DIdim/4 + 255)/256, 256>>>(X);
    prep_w_kernel<<<(DIdim*NG/4 + 255)/256, 256>>>(Wi, Wf, Wc, Wo);
    prep_u_kernel<<<(Hdim*NG/4 + 255)/256, 256>>>(Ui, Uf, Uc, Uo);

    dim3 gemm_grid((Bdim*Tdim)/128, NG/64);
    xw_mma_kernel<<<gemm_grid, 256>>>();

    lstm_kernel<<<128, 256, SMEM_BYTES>>>(init_states, out);
}

// round 11
// speedup vs baseline: 1.5531x; 1.0376x over previous
#include <cuda_runtime.h>
#include <math.h>

#define Bdim 32
#define Tdim 1024
#define DIdim 512
#define Hdim 512
#define NG (4*Hdim)

#define HROW 516                       // padded h row (floats)
#define H_SLICE_BYTES 16512u           // 8 rows * 516 * 4
#define H_HALF_BYTES  33024u           // 2 slices (16 rows)

// Scratch (device globals)
__device__ float    g_G[Tdim*Bdim*NG];        // [t][b][gate*512+j] = x@W + bias
__device__ unsigned g_A[Tdim*Bdim*DIdim];     // tf32(X) gathered, row m=t*32+b
__device__ unsigned g_Wt[DIdim*NG];           // tf32(W) fused [k][gate*512+c]
__device__ unsigned g_Ut[Hdim*NG];            // tf32(U) fused block-interleaved
__device__ float    g_bias[NG];
__device__ __align__(16) float g_h[2][32*HROW];  // tf32-valued h, PADDED, double-buffered
__device__ unsigned int g_bar;                // grid barrier counter

__device__ __forceinline__ unsigned f2tf32(float f) {
    unsigned r;
    asm("cvt.rna.tf32.f32 %0, %1;" : "=r"(r) : "f"(f));
    return r;
}

__device__ __forceinline__ void mma_tf32(float* d, const unsigned* a, const unsigned* b) {
    asm volatile(
        "mma.sync.aligned.m16n8k8.row.col.f32.tf32.tf32.f32 "
        "{%0,%1,%2,%3}, {%4,%5,%6,%7}, {%8,%9}, {%0,%1,%2,%3};"
        : "+f"(d[0]), "+f"(d[1]), "+f"(d[2]), "+f"(d[3])
        : "r"(a[0]), "r"(a[1]), "r"(a[2]), "r"(a[3]), "r"(b[0]), "r"(b[1]));
}

__device__ __forceinline__ float tanh_fast(float x) {
    float e = __expf(2.0f * x);
    return 1.0f - __fdividef(2.0f, e + 1.0f);   // inf-safe
}
__device__ __forceinline__ float sigmoid_fast(float x) {
    return __fdividef(1.0f, 1.0f + __expf(-x));
}

__device__ __forceinline__ void cp_async16(unsigned smem_dst, const void* gsrc) {
    asm volatile("cp.async.cg.shared.global [%0], [%1], 16;"
                 :: "r"(smem_dst), "l"(gsrc) : "memory");
}

// ---------------------------------------------------------------------------
__global__ void init_kernel(const float* __restrict__ init_states,
                            const float* __restrict__ bi, const float* __restrict__ bf,
                            const float* __restrict__ bc, const float* __restrict__ bo)
{
    int i = blockIdx.x * blockDim.x + threadIdx.x;
    if (i < Bdim*Hdim) {
        int b = i >> 9, j = i & 511;
        g_h[0][b*HROW + j] = __uint_as_float(f2tf32(init_states[i]));  // tf32-rounded h0
    }
    if (i < NG) {
        int gate = i >> 9, c = i & 511;
        const float* b = (gate==0) ? bi : (gate==1) ? bf : (gate==2) ? bc : bo;
        g_bias[i] = b[c];
    }
    if (i == 0) g_bar = 0u;
}

// ---------------------------------------------------------------------------
__global__ __launch_bounds__(256) void prep_x_kernel(const float* __restrict__ X) {
    int idx = blockIdx.x * blockDim.x + threadIdx.x;
    int m  = idx >> 7;
    int k4 = idx & 127;
    int b = m & 31, t = m >> 5;
    float4 v = *(const float4*)(X + ((size_t)b * Tdim + t) * DIdim + k4*4);
    uint4 o;
    o.x = f2tf32(v.x); o.y = f2tf32(v.y); o.z = f2tf32(v.z); o.w = f2tf32(v.w);
    *(uint4*)(g_A + (size_t)m * DIdim + k4*4) = o;
}

__global__ __launch_bounds__(256) void prep_w_kernel(
    const float* __restrict__ Wi, const float* __restrict__ Wf,
    const float* __restrict__ Wc, const float* __restrict__ Wo)
{
    int idx = blockIdx.x * blockDim.x + threadIdx.x;
    int gate = idx >> 16;
    int rem  = idx & 65535;
    int k  = rem >> 7;
    int c4 = rem & 127;
    const float* W = (gate==0) ? Wi : (gate==1) ? Wf : (gate==2) ? Wc : Wo;
    float4 v = *(const float4*)(W + (size_t)k * Hdim + c4*4);
    uint4 o;
    o.x = f2tf32(v.x); o.y = f2tf32(v.y); o.z = f2tf32(v.z); o.w = f2tf32(v.w);
    *(uint4*)(g_Wt + (size_t)k * NG + gate*512 + c4*4) = o;
}

// U fused + block-interleaved: g_Ut[k][ (j>>2)*16 + gate*4 + (j&3) ]
__global__ __launch_bounds__(256) void prep_u_kernel(
    const float* __restrict__ Ui, const float* __restrict__ Uf,
    const float* __restrict__ Uc, const float* __restrict__ Uo)
{
    int idx = blockIdx.x * blockDim.x + threadIdx.x;
    int gate = idx >> 16;
    int rem  = idx & 65535;
    int k  = rem >> 7;
    int jq = rem & 127;
    const float* U = (gate==0) ? Ui : (gate==1) ? Uf : (gate==2) ? Uc : Uo;
    float4 v = *(const float4*)(U + (size_t)k * Hdim + jq*4);
    uint4 o;
    o.x = f2tf32(v.x); o.y = f2tf32(v.y); o.z = f2tf32(v.z); o.w = f2tf32(v.w);
    *(uint4*)(g_Ut + (size_t)k * NG + jq*16 + gate*4) = o;
}

// ---------------------------------------------------------------------------
// xw GEMM with 2-stage cp.async pipeline: C[32768,2048] = A @ Wt + bias -> g_G
// Fragment maps identical to the verified kernel; only staging is pipelined.
// ---------------------------------------------------------------------------
#define AS_PAD 36
#define BS_PAD 68
#define XW_STAGE_A (128*AS_PAD)           // uints
#define XW_STAGE_B (32*BS_PAD)
#define XW_STAGE   (XW_STAGE_A + XW_STAGE_B)
#define XW_SMEM_BYTES (2*XW_STAGE*4)      // 54272 B

__global__ __launch_bounds__(256) void xw_mma_kernel() {
    extern __shared__ unsigned smx[];

    const int tid = threadIdx.x;
    const int wid = tid >> 5;
    const int lane = tid & 31;
    const int gid = lane >> 2;
    const int tig = lane & 3;

    const int warp_m = (wid & 3) * 32;
    const int warp_n = (wid >> 2) * 32;

    const int mbase = blockIdx.x * 128;
    const int nbase = blockIdx.y * 64;

    unsigned smem_u32;
    asm("{ .reg .u64 t0; cvta.to.shared.u64 t0, %1; cvt.u32.u64 %0, t0; }"
        : "=r"(smem_u32) : "l"(smx));

    // staging indices (same distribution as verified kernel)
    const int a_row[4] = { (tid)>>3, (tid+256)>>3, (tid+512)>>3, (tid+768)>>3 };
    const int a_k4  = (tid & 7) * 4;
    const int b_krow[2] = { tid>>4, (tid+256)>>4 };
    const int b_n4  = (tid & 15) * 4;

    // issue one k-chunk into stage s
    auto issue_chunk = [&](int k0, int s) {
        unsigned base = smem_u32 + s * XW_STAGE * 4;
        #pragma unroll
        for (int r = 0; r < 4; r++) {
            const void* src = g_A + (size_t)(mbase + a_row[r]) * DIdim + k0 + a_k4;
            cp_async16(base + (a_row[r]*AS_PAD + a_k4)*4, src);
        }
        #pragma unroll
        for (int r = 0; r < 2; r++) {
            const void* src = g_Wt + (size_t)(k0 + b_krow[r]) * NG + nbase + b_n4;
            cp_async16(base + (XW_STAGE_A + b_krow[r]*BS_PAD + b_n4)*4, src);
        }
        asm volatile("cp.async.commit_group;" ::: "memory");
    };

    float acc[2][4][4];
    #pragma unroll
    for (int mt = 0; mt < 2; mt++)
        #pragma unroll
        for (int nt = 0; nt < 4; nt++)
            #pragma unroll
            for (int r = 0; r < 4; r++) acc[mt][nt][r] = 0.f;

    issue_chunk(0, 0);

    for (int i = 0; i < 16; i++) {
        if (i < 15) {
            issue_chunk((i+1)*32, (i+1) & 1);
            asm volatile("cp.async.wait_group 1;" ::: "memory");
        } else {
            asm volatile("cp.async.wait_group 0;" ::: "memory");
        }
        __syncthreads();

        const unsigned* As = smx + (i & 1) * XW_STAGE;
        const unsigned* Bs = As + XW_STAGE_A;

        #pragma unroll
        for (int ks = 0; ks < 4; ks++) {
            const int k8 = ks * 8;
            unsigned af[2][4];
            #pragma unroll
            for (int mt = 0; mt < 2; mt++) {
                int row = warp_m + mt*16 + gid;
                af[mt][0] = As[(row    ) * AS_PAD + k8 + tig    ];
                af[mt][1] = As[(row + 8) * AS_PAD + k8 + tig    ];
                af[mt][2] = As[(row    ) * AS_PAD + k8 + tig + 4];
                af[mt][3] = As[(row + 8) * AS_PAD + k8 + tig + 4];
            }
            unsigned bf2[4][2];
            #pragma unroll
            for (int nt = 0; nt < 4; nt++) {
                int col = warp_n + nt*8 + gid;
                bf2[nt][0] = Bs[(k8 + tig    ) * BS_PAD + col];
                bf2[nt][1] = Bs[(k8 + tig + 4) * BS_PAD + col];
            }
            #pragma unroll
            for (int mt = 0; mt < 2; mt++)
                #pragma unroll
                for (int nt = 0; nt < 4; nt++)
                    mma_tf32(acc[mt][nt], af[mt], bf2[nt]);
        }
        __syncthreads();   // all reads of this stage done before it's re-filled
    }

    #pragma unroll
    for (int mt = 0; mt < 2; mt++) {
        #pragma unroll
        for (int nt = 0; nt < 4; nt++) {
            int col = nbase + warp_n + nt*8 + 2*tig;
            float b0 = g_bias[col];
            float b1 = g_bias[col + 1];
            int row0 = mbase + warp_m + mt*16 + gid;
            float2 o0 = make_float2(acc[mt][nt][0] + b0, acc[mt][nt][1] + b1);
            float2 o1 = make_float2(acc[mt][nt][2] + b0, acc[mt][nt][3] + b1);
            *(float2*)(g_G + (size_t)row0 * NG + col)       = o0;
            *(float2*)(g_G + (size_t)(row0 + 8) * NG + col) = o1;
        }
    }
}

// ---------------------------------------------------------------------------
// Persistent tensor-core recurrence (structure verified at 3234us).
// NEW this round: each nt mma chain split into 2 sub-chains (even/odd ks),
// halving the dependent-HMMA depth (16 -> 8); merged at stash.
// ---------------------------------------------------------------------------
#define SH_H 0
#define SH_P 16512                       // floats (== 32*516)
#define SH_TOTAL (SH_P + 8*290)          // floats
#define SMEM_BYTES (SH_TOTAL*4 + 16)     // + two mbarriers

__global__ __launch_bounds__(256,1) __cluster_dims__(4,1,1)
void lstm_kernel(const float* __restrict__ init_states,
                 float* __restrict__ out)
{
    extern __shared__ __align__(16) float smf[];

    const int tid  = threadIdx.x;
    const int w    = tid >> 5;
    const int lane = tid & 31;
    const int gid  = lane >> 2;
    const int tig  = lane & 3;
    const int kh   = w & 3;        // k-quarter (128 k each)
    const int mt   = w >> 2;       // m-tile (16 batches each)
    const int jb   = blockIdx.x * 4;
    const int kbase = kh * 128;

    unsigned smem_u32;
    asm("{ .reg .u64 t0; cvta.to.shared.u64 t0, %1; cvt.u32.u64 %0, t0; }"
        : "=r"(smem_u32) : "l"(smf));
    const unsigned mbar0 = smem_u32 + SH_TOTAL*4;
    const unsigned mbar1 = mbar0 + 8;
    const unsigned my_wait_mbar = mt ? mbar1 : mbar0;

    unsigned rank;
    asm("mov.u32 %0, %%cluster_ctarank;" : "=r"(rank));
    const unsigned my_tma_mbar = (rank >> 1) ? mbar1 : mbar0;

    // --- preload U fragments into registers (once): ub[nt][ks][2] ---
    unsigned ub[2][16][2];
    {
        #pragma unroll
        for (int nt = 0; nt < 2; nt++) {
            const unsigned* Ucol = g_Ut + (size_t)kbase * NG + blockIdx.x*16 + nt*8 + gid;
            #pragma unroll
            for (int ks = 0; ks < 16; ks++) {
                ub[nt][ks][0] = Ucol[(size_t)(ks*8 + tig    ) * NG];
                ub[nt][ks][1] = Ucol[(size_t)(ks*8 + tig + 4) * NG];
            }
        }
    }

    // owner mapping (tid < 128): one (batch, jj) cell each
    const int o_b  = tid >> 2;     // 0..31
    const int o_jj = tid & 3;
    const int o_mt = o_b >> 4;
    const int o_row = o_b & 15;
    float cstate = 0.f;
    if (tid < 128) cstate = init_states[Bdim*Hdim + o_b*Hdim + jb + o_jj];

    // mbarrier init + cluster sync (peers' multicast needs my mbars live)
    if (tid == 0) {
        asm volatile("mbarrier.init.shared.b64 [%0], 1;" :: "r"(mbar0) : "memory");
        asm volatile("mbarrier.init.shared.b64 [%0], 1;" :: "r"(mbar1) : "memory");
    }
    __syncthreads();
    asm volatile("barrier.cluster.arrive.aligned;" ::: "memory");
    asm volatile("barrier.cluster.wait.aligned;" ::: "memory");

    float hn = 0.f;   // carried for deferred out-store

    for (int t = 0; t < Tdim; t++) {
        // ---- pipelined cooperative-sliced TMA multicast of h ----
        if (tid == 0) {
            asm volatile("mbarrier.arrive.expect_tx.shared.b64 _, [%0], %1;"
                         :: "r"(mbar0), "r"(H_HALF_BYTES) : "memory");
            asm volatile("mbarrier.arrive.expect_tx.shared.b64 _, [%0], %1;"
                         :: "r"(mbar1), "r"(H_HALF_BYTES) : "memory");
            const char* src = (const char*)(g_h[t & 1]) + rank * H_SLICE_BYTES;
            unsigned dst = smem_u32 + rank * H_SLICE_BYTES;
            asm volatile(
                "cp.async.bulk.shared::cluster.global.mbarrier::complete_tx::bytes.multicast::cluster "
                "[%0], [%1], %2, [%3], %4;"
                :: "r"(dst), "l"(src), "r"(H_SLICE_BYTES), "r"(my_tma_mbar),
                   "h"((unsigned short)0xF) : "memory");
        }

        // prefetch G (DRAM; consumed after mma+reduce) — overlaps TMA
        float pg0=0.f, pg1=0.f, pg2=0.f, pg3=0.f;
        if (tid < 128) {
            const float* gr = g_G + ((size_t)t * Bdim + o_b) * NG + jb + o_jj;
            pg0 = __ldcg(gr);
            pg1 = __ldcg(gr + 512);
            pg2 = __ldcg(gr + 1024);
            pg3 = __ldcg(gr + 1536);
        }

        // wait only for my half (warps mt=0: batches 0-15; mt=1: 16-31)
        {
            unsigned parity = t & 1;
            asm volatile(
                "{\n\t.reg .pred P;\n"
                "W%=:\n\t"
                "mbarrier.try_wait.parity.acquire.cta.shared::cta.b64 P, [%0], %1, 0x989680;\n\t"
                "@P bra D%=;\n\t"
                "bra W%=;\n"
                "D%=:\n\t}"
                :: "r"(my_wait_mbar), "r"(parity) : "memory");
        }

        // mma: warp tile m16 x n16, K=128; 4 sub-chains (2 nt x even/odd ks)
        float acc0[2][4], acc1[2][4];
        #pragma unroll
        for (int nt = 0; nt < 2; nt++)
            #pragma unroll
            for (int r = 0; r < 4; r++) { acc0[nt][r] = 0.f; acc1[nt][r] = 0.f; }
        {
            const int row = mt*16 + gid;
            const unsigned* hs = (const unsigned*)&smf[SH_H + row*HROW + kbase + tig];
            #pragma unroll
            for (int ks = 0; ks < 16; ks += 2) {
                unsigned afA[4], afB[4];
                afA[0] = hs[ks*8];
                afA[1] = hs[ks*8 + 8*HROW];
                afA[2] = hs[ks*8 + 4];
                afA[3] = hs[ks*8 + 8*HROW + 4];
                afB[0] = hs[(ks+1)*8];
                afB[1] = hs[(ks+1)*8 + 8*HROW];
                afB[2] = hs[(ks+1)*8 + 4];
                afB[3] = hs[(ks+1)*8 + 8*HROW + 4];
                mma_tf32(acc0[0], afA, ub[0][ks]);
                mma_tf32(acc0[1], afA, ub[1][ks]);
                mma_tf32(acc1[0], afB, ub[0][ks+1]);
                mma_tf32(acc1[1], afB, ub[1][ks+1]);
            }
        }
        __syncthreads();   // all lanes done reading smem h (TMA next step rewrites)

        // stash merged partials: pbuf[w][row16][n16] (row stride 18, blk 290)
        {
            float* pb = &smf[SH_P + w*290];
            #pragma unroll
            for (int nt = 0; nt < 2; nt++) {
                *(float2*)&pb[ gid     *18 + nt*8 + 2*tig] =
                    make_float2(acc0[nt][0] + acc1[nt][0], acc0[nt][1] + acc1[nt][1]);
                *(float2*)&pb[(gid + 8)*18 + nt*8 + 2*tig] =
                    make_float2(acc0[nt][2] + acc1[nt][2], acc0[nt][3] + acc1[nt][3]);
            }
        }
        __syncthreads();

        // owners: 4-way k-reduce + G + LSTM cell; write tf32-rounded h
        if (tid < 128) {
            const float* pb = &smf[SH_P + (o_mt*4)*290 + o_row*18 + o_jj];
            float z0 = pg0, z1 = pg1, z2 = pg2, z3 = pg3;
            #pragma unroll
            for (int q = 0; q < 4; q++) {
                const float* r = pb + q*290;
                z0 += r[0];    // i
                z1 += r[4];    // f
                z2 += r[8];    // g
                z3 += r[12];   // o
            }
            float iv = sigmoid_fast(z0);
            float fv = sigmoid_fast(z1);
            float gv = tanh_fast(z2);
            float ov = sigmoid_fast(z3);
            cstate = fv * cstate + iv * gv;
            hn = ov * tanh_fast(cstate);
            g_h[(t+1) & 1][o_b*HROW + jb + o_jj] = __uint_as_float(f2tf32(hn));
        }
        __syncthreads();    // all h stores done (CTA scope)

        // ---- grid barrier: ONE fence + one atomic arrive per CTA ----
        if (tid == 0) {
            asm volatile("membar.gl;" ::: "memory");
            atomicAdd(&g_bar, 1u);
        }

        // deferred out store (full-precision hn) overlaps the barrier wait
        if (tid < 128) {
            out[((size_t)o_b * Tdim + t) * Hdim + jb + o_jj] = hn;
        }

        if (tid == 0) {
            unsigned target = (unsigned)gridDim.x * (unsigned)(t + 1);
            unsigned v;
            do {
                asm volatile("ld.acquire.gpu.global.u32 %0, [%1];"
                             : "=r"(v) : "l"(&g_bar) : "memory");
            } while (v < target);
        }
        __syncthreads();
    }

    asm volatile("barrier.cluster.arrive.aligned;" ::: "memory");
    asm volatile("barrier.cluster.wait.aligned;" ::: "memory");
}

// ---------------------------------------------------------------------------
extern "C" void kernel_launch(void* const* d_in, const int* in_sizes, int n_in,
                              void* d_out, int out_size) {
    const float* X           = (const float*)d_in[0];
    const float* init_states = (const float*)d_in[1];
    const float* Wi = (const float*)d_in[2];
    const float* Ui = (const float*)d_in[3];
    const float* bi = (const float*)d_in[4];
    const float* Wf = (const float*)d_in[5];
    const float* Uf = (const float*)d_in[6];
    const float* bf = (const float*)d_in[7];
    const float* Wc = (const float*)d_in[8];
    const float* Uc = (const float*)d_in[9];
    const float* bc = (const float*)d_in[10];
    const float* Wo = (const float*)d_in[11];
    const float* Uo = (const float*)d_in[12];
    const float* bo = (const float*)d_in[13];
    float* out = (float*)d_out;

    cudaFuncSetAttribute(lstm_kernel, cudaFuncAttributeMaxDynamicSharedMemorySize,
                         SMEM_BYTES);
    cudaFuncSetAttribute(xw_mma_kernel, cudaFuncAttributeMaxDynamicSharedMemorySize,
                         XW_SMEM_BYTES);

    init_kernel<<<(Bdim*Hdim + 255)/256, 256>>>(init_states, bi, bf, bc, bo);

    prep_x_kernel<<<(Tdim*Bdim*DIdim/4 + 255)/256, 256>>>(X);
    prep_w_kernel<<<(DIdim*NG/4 + 255)/256, 256>>>(Wi, Wf, Wc, Wo);
    prep_u_kernel<<<(Hdim*NG/4 + 255)/256, 256>>>(Ui, Uf, Uc, Uo);

    dim3 gemm_grid((Bdim*Tdim)/128, NG/64);
    xw_mma_kernel<<<gemm_grid, 256, XW_SMEM_BYTES>>>();

    lstm_kernel<<<128, 256, SMEM_BYTES>>>(init_states, out);
}

// round 12
// speedup vs baseline: 1.6138x; 1.0391x over previous
#include <cuda_runtime.h>
#include <math.h>

#define Bdim 32
#define Tdim 1024
#define DIdim 512
#define Hdim 512
#define NG (4*Hdim)

#define HROW 516                       // padded h row (floats)
#define H_SLICE_BYTES 16512u           // 8 rows * 516 * 4
#define H_HALF_BYTES  33024u           // 2 slices (16 rows)

// Scratch (device globals)
__device__ float    g_G[Tdim*Bdim*NG];        // [t][b][gate*512+j] = x@W + bias
__device__ unsigned g_A[Tdim*Bdim*DIdim];     // tf32(X) gathered, row m=t*32+b
__device__ unsigned g_Wt[DIdim*NG];           // tf32(W) fused [k][gate*512+c]
__device__ unsigned g_Ut[Hdim*NG];            // tf32(U) fused block-interleaved
__device__ float    g_bias[NG];
__device__ __align__(16) float g_h[2][32*HROW];  // tf32-valued h, PADDED, double-buffered
__device__ unsigned int g_bar;                // grid barrier counter

__device__ __forceinline__ unsigned f2tf32(float f) {
    unsigned r;
    asm("cvt.rna.tf32.f32 %0, %1;" : "=r"(r) : "f"(f));
    return r;
}

__device__ __forceinline__ void mma_tf32(float* d, const unsigned* a, const unsigned* b) {
    asm volatile(
        "mma.sync.aligned.m16n8k8.row.col.f32.tf32.tf32.f32 "
        "{%0,%1,%2,%3}, {%4,%5,%6,%7}, {%8,%9}, {%0,%1,%2,%3};"
        : "+f"(d[0]), "+f"(d[1]), "+f"(d[2]), "+f"(d[3])
        : "r"(a[0]), "r"(a[1]), "r"(a[2]), "r"(a[3]), "r"(b[0]), "r"(b[1]));
}

__device__ __forceinline__ float tanh_fast(float x) {
    float e = __expf(2.0f * x);
    return 1.0f - __fdividef(2.0f, e + 1.0f);   // inf-safe
}
__device__ __forceinline__ float sigmoid_fast(float x) {
    return __fdividef(1.0f, 1.0f + __expf(-x));
}

__device__ __forceinline__ void cp_async16(unsigned smem_dst, const void* gsrc) {
    asm volatile("cp.async.cg.shared.global [%0], [%1], 16;"
                 :: "r"(smem_dst), "l"(gsrc) : "memory");
}

// ---------------------------------------------------------------------------
__global__ void init_kernel(const float* __restrict__ init_states,
                            const float* __restrict__ bi, const float* __restrict__ bf,
                            const float* __restrict__ bc, const float* __restrict__ bo)
{
    int i = blockIdx.x * blockDim.x + threadIdx.x;
    if (i < Bdim*Hdim) {
        int b = i >> 9, j = i & 511;
        g_h[0][b*HROW + j] = __uint_as_float(f2tf32(init_states[i]));  // tf32-rounded h0
    }
    if (i < NG) {
        int gate = i >> 9, c = i & 511;
        const float* b = (gate==0) ? bi : (gate==1) ? bf : (gate==2) ? bc : bo;
        g_bias[i] = b[c];
    }
    if (i == 0) g_bar = 0u;
}

// ---------------------------------------------------------------------------
__global__ __launch_bounds__(256) void prep_x_kernel(const float* __restrict__ X) {
    int idx = blockIdx.x * blockDim.x + threadIdx.x;
    int m  = idx >> 7;
    int k4 = idx & 127;
    int b = m & 31, t = m >> 5;
    float4 v = *(const float4*)(X + ((size_t)b * Tdim + t) * DIdim + k4*4);
    uint4 o;
    o.x = f2tf32(v.x); o.y = f2tf32(v.y); o.z = f2tf32(v.z); o.w = f2tf32(v.w);
    *(uint4*)(g_A + (size_t)m * DIdim + k4*4) = o;
}

__global__ __launch_bounds__(256) void prep_w_kernel(
    const float* __restrict__ Wi, const float* __restrict__ Wf,
    const float* __restrict__ Wc, const float* __restrict__ Wo)
{
    int idx = blockIdx.x * blockDim.x + threadIdx.x;
    int gate = idx >> 16;
    int rem  = idx & 65535;
    int k  = rem >> 7;
    int c4 = rem & 127;
    const float* W = (gate==0) ? Wi : (gate==1) ? Wf : (gate==2) ? Wc : Wo;
    float4 v = *(const float4*)(W + (size_t)k * Hdim + c4*4);
    uint4 o;
    o.x = f2tf32(v.x); o.y = f2tf32(v.y); o.z = f2tf32(v.z); o.w = f2tf32(v.w);
    *(uint4*)(g_Wt + (size_t)k * NG + gate*512 + c4*4) = o;
}

// U fused + block-interleaved: g_Ut[k][ (j>>2)*16 + gate*4 + (j&3) ]
__global__ __launch_bounds__(256) void prep_u_kernel(
    const float* __restrict__ Ui, const float* __restrict__ Uf,
    const float* __restrict__ Uc, const float* __restrict__ Uo)
{
    int idx = blockIdx.x * blockDim.x + threadIdx.x;
    int gate = idx >> 16;
    int rem  = idx & 65535;
    int k  = rem >> 7;
    int jq = rem & 127;
    const float* U = (gate==0) ? Ui : (gate==1) ? Uf : (gate==2) ? Uc : Uo;
    float4 v = *(const float4*)(U + (size_t)k * Hdim + jq*4);
    uint4 o;
    o.x = f2tf32(v.x); o.y = f2tf32(v.y); o.z = f2tf32(v.z); o.w = f2tf32(v.w);
    *(uint4*)(g_Ut + (size_t)k * NG + jq*16 + gate*4) = o;
}

// ---------------------------------------------------------------------------
// xw GEMM, 128x128 CTA tile + 2-stage cp.async pipeline.
// Halves A and Wt L2 traffic vs 128x64 (xw was LTS-bound at ~5TB/s).
// Same fragment maps; warp tile m32 x n64 (nt loop 0..7).
// ---------------------------------------------------------------------------
#define AS_PAD 36
#define BS_PAD 132
#define XW_STAGE_A (128*AS_PAD)           // 4608 uints
#define XW_STAGE_B (32*BS_PAD)            // 4224 uints
#define XW_STAGE   (XW_STAGE_A + XW_STAGE_B)
#define XW_SMEM_BYTES (2*XW_STAGE*4)      // 70656 B

__global__ __launch_bounds__(256) void xw_mma_kernel() {
    extern __shared__ unsigned smx[];

    const int tid = threadIdx.x;
    const int wid = tid >> 5;
    const int lane = tid & 31;
    const int gid = lane >> 2;
    const int tig = lane & 3;

    const int warp_m = (wid & 3) * 32;
    const int warp_n = (wid >> 2) * 64;

    const int mbase = blockIdx.x * 128;
    const int nbase = blockIdx.y * 128;

    unsigned smem_u32;
    asm("{ .reg .u64 t0; cvta.to.shared.u64 t0, %1; cvt.u32.u64 %0, t0; }"
        : "=r"(smem_u32) : "l"(smx));

    // staging indices
    const int a_row[4] = { (tid)>>3, (tid+256)>>3, (tid+512)>>3, (tid+768)>>3 };
    const int a_k4  = (tid & 7) * 4;
    const int b_krow[4] = { tid>>5, (tid+256)>>5, (tid+512)>>5, (tid+768)>>5 };
    const int b_n4  = (tid & 31) * 4;

    auto issue_chunk = [&](int k0, int s) {
        unsigned base = smem_u32 + s * XW_STAGE * 4;
        #pragma unroll
        for (int r = 0; r < 4; r++) {
            const void* src = g_A + (size_t)(mbase + a_row[r]) * DIdim + k0 + a_k4;
            cp_async16(base + (a_row[r]*AS_PAD + a_k4)*4, src);
        }
        #pragma unroll
        for (int r = 0; r < 4; r++) {
            const void* src = g_Wt + (size_t)(k0 + b_krow[r]) * NG + nbase + b_n4;
            cp_async16(base + (XW_STAGE_A + b_krow[r]*BS_PAD + b_n4)*4, src);
        }
        asm volatile("cp.async.commit_group;" ::: "memory");
    };

    float acc[2][8][4];
    #pragma unroll
    for (int mt = 0; mt < 2; mt++)
        #pragma unroll
        for (int nt = 0; nt < 8; nt++)
            #pragma unroll
            for (int r = 0; r < 4; r++) acc[mt][nt][r] = 0.f;

    issue_chunk(0, 0);

    for (int i = 0; i < 16; i++) {
        if (i < 15) {
            issue_chunk((i+1)*32, (i+1) & 1);
            asm volatile("cp.async.wait_group 1;" ::: "memory");
        } else {
            asm volatile("cp.async.wait_group 0;" ::: "memory");
        }
        __syncthreads();

        const unsigned* As = smx + (i & 1) * XW_STAGE;
        const unsigned* Bs = As + XW_STAGE_A;

        #pragma unroll
        for (int ks = 0; ks < 4; ks++) {
            const int k8 = ks * 8;
            unsigned af[2][4];
            #pragma unroll
            for (int mt = 0; mt < 2; mt++) {
                int row = warp_m + mt*16 + gid;
                af[mt][0] = As[(row    ) * AS_PAD + k8 + tig    ];
                af[mt][1] = As[(row + 8) * AS_PAD + k8 + tig    ];
                af[mt][2] = As[(row    ) * AS_PAD + k8 + tig + 4];
                af[mt][3] = As[(row + 8) * AS_PAD + k8 + tig + 4];
            }
            unsigned bf2[8][2];
            #pragma unroll
            for (int nt = 0; nt < 8; nt++) {
                int col = warp_n + nt*8 + gid;
                bf2[nt][0] = Bs[(k8 + tig    ) * BS_PAD + col];
                bf2[nt][1] = Bs[(k8 + tig + 4) * BS_PAD + col];
            }
            #pragma unroll
            for (int mt = 0; mt < 2; mt++)
                #pragma unroll
                for (int nt = 0; nt < 8; nt++)
                    mma_tf32(acc[mt][nt], af[mt], bf2[nt]);
        }
        __syncthreads();   // all reads of this stage done before it's re-filled
    }

    #pragma unroll
    for (int mt = 0; mt < 2; mt++) {
        #pragma unroll
        for (int nt = 0; nt < 8; nt++) {
            int col = nbase + warp_n + nt*8 + 2*tig;
            float b0 = g_bias[col];
            float b1 = g_bias[col + 1];
            int row0 = mbase + warp_m + mt*16 + gid;
            float2 o0 = make_float2(acc[mt][nt][0] + b0, acc[mt][nt][1] + b1);
            float2 o1 = make_float2(acc[mt][nt][2] + b0, acc[mt][nt][3] + b1);
            *(float2*)(g_G + (size_t)row0 * NG + col)       = o0;
            *(float2*)(g_G + (size_t)(row0 + 8) * NG + col) = o1;
        }
    }
}

// ---------------------------------------------------------------------------
// Persistent tensor-core recurrence (verified at 3117us). This round:
// removed the redundant post-mma __syncthreads (stash targets disjoint SH_P;
// SH_H not rewritten until after the grid barrier's own syncs).
// ---------------------------------------------------------------------------
#define SH_H 0
#define SH_P 16512                       // floats (== 32*516)
#define SH_TOTAL (SH_P + 8*290)          // floats
#define SMEM_BYTES (SH_TOTAL*4 + 16)     // + two mbarriers

__global__ __launch_bounds__(256,1) __cluster_dims__(4,1,1)
void lstm_kernel(const float* __restrict__ init_states,
                 float* __restrict__ out)
{
    extern __shared__ __align__(16) float smf[];

    const int tid  = threadIdx.x;
    const int w    = tid >> 5;
    const int lane = tid & 31;
    const int gid  = lane >> 2;
    const int tig  = lane & 3;
    const int kh   = w & 3;        // k-quarter (128 k each)
    const int mt   = w >> 2;       // m-tile (16 batches each)
    const int jb   = blockIdx.x * 4;
    const int kbase = kh * 128;

    unsigned smem_u32;
    asm("{ .reg .u64 t0; cvta.to.shared.u64 t0, %1; cvt.u32.u64 %0, t0; }"
        : "=r"(smem_u32) : "l"(smf));
    const unsigned mbar0 = smem_u32 + SH_TOTAL*4;
    const unsigned mbar1 = mbar0 + 8;
    const unsigned my_wait_mbar = mt ? mbar1 : mbar0;

    unsigned rank;
    asm("mov.u32 %0, %%cluster_ctarank;" : "=r"(rank));
    const unsigned my_tma_mbar = (rank >> 1) ? mbar1 : mbar0;

    // --- preload U fragments into registers (once): ub[nt][ks][2] ---
    unsigned ub[2][16][2];
    {
        #pragma unroll
        for (int nt = 0; nt < 2; nt++) {
            const unsigned* Ucol = g_Ut + (size_t)kbase * NG + blockIdx.x*16 + nt*8 + gid;
            #pragma unroll
            for (int ks = 0; ks < 16; ks++) {
                ub[nt][ks][0] = Ucol[(size_t)(ks*8 + tig    ) * NG];
                ub[nt][ks][1] = Ucol[(size_t)(ks*8 + tig + 4) * NG];
            }
        }
    }

    // owner mapping (tid < 128): one (batch, jj) cell each
    const int o_b  = tid >> 2;     // 0..31
    const int o_jj = tid & 3;
    const int o_mt = o_b >> 4;
    const int o_row = o_b & 15;
    float cstate = 0.f;
    if (tid < 128) cstate = init_states[Bdim*Hdim + o_b*Hdim + jb + o_jj];

    // mbarrier init + cluster sync (peers' multicast needs my mbars live)
    if (tid == 0) {
        asm volatile("mbarrier.init.shared.b64 [%0], 1;" :: "r"(mbar0) : "memory");
        asm volatile("mbarrier.init.shared.b64 [%0], 1;" :: "r"(mbar1) : "memory");
    }
    __syncthreads();
    asm volatile("barrier.cluster.arrive.aligned;" ::: "memory");
    asm volatile("barrier.cluster.wait.aligned;" ::: "memory");

    float hn = 0.f;   // carried for deferred out-store

    for (int t = 0; t < Tdim; t++) {
        // ---- pipelined cooperative-sliced TMA multicast of h ----
        if (tid == 0) {
            asm volatile("mbarrier.arrive.expect_tx.shared.b64 _, [%0], %1;"
                         :: "r"(mbar0), "r"(H_HALF_BYTES) : "memory");
            asm volatile("mbarrier.arrive.expect_tx.shared.b64 _, [%0], %1;"
                         :: "r"(mbar1), "r"(H_HALF_BYTES) : "memory");
            const char* src = (const char*)(g_h[t & 1]) + rank * H_SLICE_BYTES;
            unsigned dst = smem_u32 + rank * H_SLICE_BYTES;
            asm volatile(
                "cp.async.bulk.shared::cluster.global.mbarrier::complete_tx::bytes.multicast::cluster "
                "[%0], [%1], %2, [%3], %4;"
                :: "r"(dst), "l"(src), "r"(H_SLICE_BYTES), "r"(my_tma_mbar),
                   "h"((unsigned short)0xF) : "memory");
        }

        // prefetch G (DRAM; consumed after mma+reduce) — overlaps TMA
        float pg0=0.f, pg1=0.f, pg2=0.f, pg3=0.f;
        if (tid < 128) {
            const float* gr = g_G + ((size_t)t * Bdim + o_b) * NG + jb + o_jj;
            pg0 = __ldcg(gr);
            pg1 = __ldcg(gr + 512);
            pg2 = __ldcg(gr + 1024);
            pg3 = __ldcg(gr + 1536);
        }

        // wait only for my half (warps mt=0: batches 0-15; mt=1: 16-31)
        {
            unsigned parity = t & 1;
            asm volatile(
                "{\n\t.reg .pred P;\n"
                "W%=:\n\t"
                "mbarrier.try_wait.parity.acquire.cta.shared::cta.b64 P, [%0], %1, 0x989680;\n\t"
                "@P bra D%=;\n\t"
                "bra W%=;\n"
                "D%=:\n\t}"
                :: "r"(my_wait_mbar), "r"(parity) : "memory");
        }

        // mma: warp tile m16 x n16, K=128; 4 sub-chains (2 nt x even/odd ks)
        float acc0[2][4], acc1[2][4];
        #pragma unroll
        for (int nt = 0; nt < 2; nt++)
            #pragma unroll
            for (int r = 0; r < 4; r++) { acc0[nt][r] = 0.f; acc1[nt][r] = 0.f; }
        {
            const int row = mt*16 + gid;
            const unsigned* hs = (const unsigned*)&smf[SH_H + row*HROW + kbase + tig];
            #pragma unroll
            for (int ks = 0; ks < 16; ks += 2) {
                unsigned afA[4], afB[4];
                afA[0] = hs[ks*8];
                afA[1] = hs[ks*8 + 8*HROW];
                afA[2] = hs[ks*8 + 4];
                afA[3] = hs[ks*8 + 8*HROW + 4];
                afB[0] = hs[(ks+1)*8];
                afB[1] = hs[(ks+1)*8 + 8*HROW];
                afB[2] = hs[(ks+1)*8 + 4];
                afB[3] = hs[(ks+1)*8 + 8*HROW + 4];
                mma_tf32(acc0[0], afA, ub[0][ks]);
                mma_tf32(acc0[1], afA, ub[1][ks]);
                mma_tf32(acc1[0], afB, ub[0][ks+1]);
                mma_tf32(acc1[1], afB, ub[1][ks+1]);
            }
        }
        // NOTE: no syncthreads here — stash targets SH_P (disjoint, per-warp
        // private); SH_H is not rewritten until after the grid barrier.

        // stash merged partials: pbuf[w][row16][n16] (row stride 18, blk 290)
        {
            float* pb = &smf[SH_P + w*290];
            #pragma unroll
            for (int nt = 0; nt < 2; nt++) {
                *(float2*)&pb[ gid     *18 + nt*8 + 2*tig] =
                    make_float2(acc0[nt][0] + acc1[nt][0], acc0[nt][1] + acc1[nt][1]);
                *(float2*)&pb[(gid + 8)*18 + nt*8 + 2*tig] =
                    make_float2(acc0[nt][2] + acc1[nt][2], acc0[nt][3] + acc1[nt][3]);
            }
        }
        __syncthreads();

        // owners: 4-way k-reduce + G + LSTM cell; write tf32-rounded h
        if (tid < 128) {
            const float* pb = &smf[SH_P + (o_mt*4)*290 + o_row*18 + o_jj];
            float z0 = pg0, z1 = pg1, z2 = pg2, z3 = pg3;
            #pragma unroll
            for (int q = 0; q < 4; q++) {
                const float* r = pb + q*290;
                z0 += r[0];    // i
                z1 += r[4];    // f
                z2 += r[8];    // g
                z3 += r[12];   // o
            }
            float iv = sigmoid_fast(z0);
            float fv = sigmoid_fast(z1);
            float gv = tanh_fast(z2);
            float ov = sigmoid_fast(z3);
            cstate = fv * cstate + iv * gv;
            hn = ov * tanh_fast(cstate);
            g_h[(t+1) & 1][o_b*HROW + jb + o_jj] = __uint_as_float(f2tf32(hn));
        }
        __syncthreads();    // all h stores done (CTA scope)

        // ---- grid barrier: ONE fence + one atomic arrive per CTA ----
        if (tid == 0) {
            asm volatile("membar.gl;" ::: "memory");
            atomicAdd(&g_bar, 1u);
        }

        // deferred out store (full-precision hn) overlaps the barrier wait
        if (tid < 128) {
            out[((size_t)o_b * Tdim + t) * Hdim + jb + o_jj] = hn;
        }

        if (tid == 0) {
            unsigned target = (unsigned)gridDim.x * (unsigned)(t + 1);
            unsigned v;
            do {
                asm volatile("ld.acquire.gpu.global.u32 %0, [%1];"
                             : "=r"(v) : "l"(&g_bar) : "memory");
            } while (v < target);
        }
        __syncthreads();
    }

    asm volatile("barrier.cluster.arrive.aligned;" ::: "memory");
    asm volatile("barrier.cluster.wait.aligned;" ::: "memory");
}

// ---------------------------------------------------------------------------
extern "C" void kernel_launch(void* const* d_in, const int* in_sizes, int n_in,
                              void* d_out, int out_size) {
    const float* X           = (const float*)d_in[0];
    const float* init_states = (const float*)d_in[1];
    const float* Wi = (const float*)d_in[2];
    const float* Ui = (const float*)d_in[3];
    const float* bi = (const float*)d_in[4];
    const float* Wf = (const float*)d_in[5];
    const float* Uf = (const float*)d_in[6];
    const float* bf = (const float*)d_in[7];
    const float* Wc = (const float*)d_in[8];
    const float* Uc = (const float*)d_in[9];
    const float* bc = (const float*)d_in[10];
    const float* Wo = (const float*)d_in[11];
    const float* Uo = (const float*)d_in[12];
    const float* bo = (const float*)d_in[13];
    float* out = (float*)d_out;

    cudaFuncSetAttribute(lstm_kernel, cudaFuncAttributeMaxDynamicSharedMemorySize,
                         SMEM_BYTES);
    cudaFuncSetAttribute(xw_mma_kernel, cudaFuncAttributeMaxDynamicSharedMemorySize,
                         XW_SMEM_BYTES);

    init_kernel<<<(Bdim*Hdim + 255)/256, 256>>>(init_states, bi, bf, bc, bo);

    prep_x_kernel<<<(Tdim*Bdim*DIdim/4 + 255)/256, 256>>>(X);
    prep_w_kernel<<<(DIdim*NG/4 + 255)/256, 256>>>(Wi, Wf, Wc, Wo);
    prep_u_kernel<<<(Hdim*NG/4 + 255)/256, 256>>>(Ui, Uf, Uc, Uo);

    dim3 gemm_grid((Bdim*Tdim)/128, NG/128);   // (256, 16)
    xw_mma_kernel<<<gemm_grid, 256, XW_SMEM_BYTES>>>();

    lstm_kernel<<<128, 256, SMEM_BYTES>>>(init_states, out);
}